// round 5
// baseline (speedup 1.0000x reference)
#include <cuda_runtime.h>
#include <cuda_bf16.h>
#include <cstdint>
#include <math.h>

#define BB 4
#define SS 4096
#define EE 512
#define HH 8
#define DD 64
#define CC 64
#define WW 64
#define LL 4
#define FF 2048
#define NVOC 17

#define BS (BB*SS)                 // 16384 rows
#define BSE ((size_t)BS*EE)        // 8388608
#define BHS (BB*HH*SS)             // 131072

// ---------------- device scratch (no allocations allowed) ----------------
__device__ float g_buf[12*BSE + BHS + 512 + BHS];
__device__ int   g_idx[BB*HH*CC*WW];
// transposed + bf16-split weights: per layer 4*(512*512) + 512*2048 + 2048*512 = 3145728
#define WT_LAYER 3145728
#define WT_TOT   ((size_t)LL*WT_LAYER)
__device__ __nv_bfloat16 g_wt[2*WT_TOT];   // [hi | lo]

// ================= PTX helpers =================
__device__ __forceinline__ uint32_t smem_u32(const void* p) {
    uint32_t a;
    asm("{ .reg .u64 t; cvta.to.shared.u64 t, %1; cvt.u32.u64 %0, t; }" : "=r"(a) : "l"(p));
    return a;
}
__device__ __forceinline__ void cp16(uint32_t saddr, const void* gptr) {
    asm volatile("cp.async.cg.shared.global [%0], [%1], 16;" :: "r"(saddr), "l"(gptr));
}
__device__ __forceinline__ void cp_commit() { asm volatile("cp.async.commit_group;" ::: "memory"); }
template<int N> __device__ __forceinline__ void cp_wait() { asm volatile("cp.async.wait_group %0;" :: "n"(N) : "memory"); }

#define LDSM4(r0,r1,r2,r3,addr) \
    asm volatile("ldmatrix.sync.aligned.m8n8.x4.shared.b16 {%0,%1,%2,%3}, [%4];" \
        : "=r"(r0), "=r"(r1), "=r"(r2), "=r"(r3) : "r"(addr))

#define MMA16816(c, a, b0, b1) \
    asm volatile("mma.sync.aligned.m16n8k16.row.col.f32.bf16.bf16.f32 " \
        "{%0,%1,%2,%3}, {%4,%5,%6,%7}, {%8,%9}, {%0,%1,%2,%3};" \
        : "+f"((c)[0]), "+f"((c)[1]), "+f"((c)[2]), "+f"((c)[3]) \
        : "r"((a)[0]), "r"((a)[1]), "r"((a)[2]), "r"((a)[3]), "r"(b0), "r"(b1))

// ---------------- embedding + shift-right ----------------
__global__ void embed_kernel(const int* __restrict__ value, const int* __restrict__ depth,
                             const int* __restrict__ pos, const float* __restrict__ sos,
                             const float* __restrict__ tok, const float* __restrict__ dep,
                             const float* __restrict__ pemb, float* __restrict__ x) {
    int row = blockIdx.x;
    int b = row >> 12, s = row & 4095;
    float* xr = x + (size_t)row * EE;
    if (s == 0) {
        for (int i = threadIdx.x; i < EE; i += blockDim.x) xr[i] = sos[i];
        return;
    }
    int sp = s - 1;
    int v  = value[b*SS + sp];
    int dp = depth[b*SS + sp];
    int p0 = pos[(b*SS + sp)*3 + 0];
    int p1 = pos[(b*SS + sp)*3 + 1];
    int p2 = pos[(b*SS + sp)*3 + 2];
    const float* t0 = tok + (size_t)v*EE;
    const float* d0 = dep + (size_t)dp*EE;
    const float* e0 = pemb + ((size_t)0*65 + p0)*EE;
    const float* e1 = pemb + ((size_t)1*65 + p1)*EE;
    const float* e2 = pemb + ((size_t)2*65 + p2)*EE;
    for (int i = threadIdx.x; i < EE; i += blockDim.x)
        xr[i] = t0[i] + d0[i] + e0[i] + e1[i] + e2[i];
}

// ---------------- layernorm -> bf16 hi/lo ----------------
__global__ void ln_kernel(const float* __restrict__ x, const float* __restrict__ sc,
                          const float* __restrict__ bi, __nv_bfloat16* __restrict__ ohi,
                          __nv_bfloat16* __restrict__ olo) {
    int row = blockIdx.x;
    const float* xr = x + (size_t)row * EE;
    __shared__ float red[256];
    int tid = threadIdx.x;
    float v0 = xr[tid], v1 = xr[tid + 256];
    red[tid] = v0 + v1;
    __syncthreads();
    for (int st = 128; st > 0; st >>= 1) { if (tid < st) red[tid] += red[tid + st]; __syncthreads(); }
    float mean = red[0] * (1.f/512.f);
    __syncthreads();
    float d0 = v0 - mean, d1 = v1 - mean;
    red[tid] = d0*d0 + d1*d1;
    __syncthreads();
    for (int st = 128; st > 0; st >>= 1) { if (tid < st) red[tid] += red[tid + st]; __syncthreads(); }
    float var = red[0] * (1.f/512.f);
    float r = rsqrtf(var + 1e-5f);
    float y0 = d0 * r * sc[tid]       + bi[tid];
    float y1 = d1 * r * sc[tid + 256] + bi[tid + 256];
    __nv_bfloat16 h0 = __float2bfloat16(y0);
    __nv_bfloat16 h1 = __float2bfloat16(y1);
    size_t base = (size_t)row * EE;
    ohi[base + tid]       = h0;
    ohi[base + tid + 256] = h1;
    olo[base + tid]       = __float2bfloat16(y0 - __bfloat162float(h0));
    olo[base + tid + 256] = __float2bfloat16(y1 - __bfloat162float(h1));
}

// ---------------- ALL weights transpose + bf16 split in ONE launch ----------------
// W[K,N] -> WT hi/lo [N,K]. Per-layer tiles: 4*256 (QKVO) + 1024 (W1) + 1024 (W2) = 3072.
__global__ void wtrans_all(const float* __restrict__ Wq, const float* __restrict__ Wk,
                           const float* __restrict__ Wv, const float* __restrict__ Wo,
                           const float* __restrict__ W1, const float* __restrict__ W2,
                           __nv_bfloat16* __restrict__ hi_base, __nv_bfloat16* __restrict__ lo_base) {
    __shared__ float t[32][33];
    int bid = blockIdx.x;
    int l = bid / 3072, r = bid % 3072;
    const float* W; int K, N, tile; size_t off;
    if (r < 1024) {
        int ty = r >> 8; tile = r & 255; K = 512; N = 512;
        const float* Ws = (ty == 0) ? Wq : (ty == 1) ? Wk : (ty == 2) ? Wv : Wo;
        W = Ws + (size_t)l*512*512;
        off = (size_t)l*WT_LAYER + (size_t)ty*262144;
    } else if (r < 2048) {
        tile = r - 1024; K = 512; N = 2048;
        W = W1 + (size_t)l*512*2048;
        off = (size_t)l*WT_LAYER + 1048576;
    } else {
        tile = r - 2048; K = 2048; N = 512;
        W = W2 + (size_t)l*2048*512;
        off = (size_t)l*WT_LAYER + 2097152;
    }
    __nv_bfloat16* hi = hi_base + off;
    __nv_bfloat16* lo = lo_base + off;
    int tilesN = N >> 5;
    int n0 = (tile % tilesN) * 32, k0 = (tile / tilesN) * 32;
    for (int i = threadIdx.y; i < 32; i += 8)
        t[i][threadIdx.x] = W[(size_t)(k0 + i) * N + n0 + threadIdx.x];
    __syncthreads();
    for (int i = threadIdx.y; i < 32; i += 8) {
        int n = n0 + i, k = k0 + threadIdx.x;
        float v = t[threadIdx.x][i];
        __nv_bfloat16 h = __float2bfloat16(v);
        hi[(size_t)n*K + k] = h;
        lo[(size_t)n*K + k] = __float2bfloat16(v - __bfloat162float(h));
    }
}

// ---------------- HMMA GEMM: C[M,N] = A[M,K] @ B^T (B stored [N,K]) ----------------
// bf16x3: D = Ahi*Bhi + Alo*Bhi + Ahi*Blo, fp32 accumulate.
// K-chunk 32 (64B rows), 4-stage cp.async pipeline.
// MODE: 0 = splithead fp32 (QKV)   1 = resid fp32 (Wo)
//       2 = bias+gelu -> bf16 hi/lo (W1)   3 = bias+resid fp32 (W2)
#define STG_B 8192                  // per-array stage: 128 rows * 64 B
#define STAGE_B (4*STG_B)           // Ahi|Alo|Bhi|Blo = 32 KB
#define NSTAGES 4
#define GT_SMEM (NSTAGES*STAGE_B)   // 131072

// 64B-row swizzle, conflict-free for cp.async stores + ldmatrix (verified spans)
__device__ __forceinline__ uint32_t swz64(int r, int u) {
    return (uint32_t)(r*64 + ((u ^ ((r >> 1) & 3)) << 4));
}

__device__ __forceinline__ float gelu_f(float x) {
    float x3 = x * x * x;
    return 0.5f * x * (1.0f + tanhf(0.7978845608028654f * (x + 0.044715f * x3)));
}

template<int MODE>
__global__ void __launch_bounds__(256) gemm_mma(
    const __nv_bfloat16* __restrict__ Ahi, const __nv_bfloat16* __restrict__ Alo,
    const __nv_bfloat16* __restrict__ Bhi, const __nv_bfloat16* __restrict__ Blo,
    const float* __restrict__ bias, float* __restrict__ Cf,
    __nv_bfloat16* __restrict__ Chi, __nv_bfloat16* __restrict__ Clo,
    int M, int N, int K)
{
    extern __shared__ char sm[];
    uint32_t sb = smem_u32(sm);
    int tid = threadIdx.x, wid = tid >> 5, lane = tid & 31;
    int mrow = blockIdx.y * 128, ncol = blockIdx.x * 128;
    int wm = (wid >> 1) * 32;       // 4 m-warps
    int wn = (wid & 1) * 64;        // 2 n-warps

    // cp.async loader: thread -> (row, two 16B units)
    int lr = tid >> 1;
    int lu0 = (tid & 1) * 2;        // units {0,1} or {2,3}
    const __nv_bfloat16* gAh = Ahi + (size_t)(mrow + lr) * K;
    const __nv_bfloat16* gAl = Alo + (size_t)(mrow + lr) * K;
    const __nv_bfloat16* gBh = Bhi + (size_t)(ncol + lr) * K;
    const __nv_bfloat16* gBl = Blo + (size_t)(ncol + lr) * K;

    int nch = K >> 5;               // K-chunks of 32

    // fragment address components (proven in round 4)
    const int m_off = ((lane >> 3) & 1) * 8 + (lane & 7);
    const int a_ku  = (lane >> 4);
    const int n_off = ((lane >> 4) << 3) + (lane & 7);
    const int b_ku  = ((lane >> 3) & 1);

    float acc[2][8][4] = {};

    // prologue: fill NSTAGES-1 stages
    #pragma unroll
    for (int c = 0; c < NSTAGES-1; c++) {
        uint32_t bufb = sb + c * STAGE_B;
        int koff = c << 5;
        #pragma unroll
        for (int j = 0; j < 2; j++) {
            int u = lu0 + j;
            uint32_t so = swz64(lr, u);
            int ge = koff + u * 8;
            cp16(bufb + 0*STG_B + so, gAh + ge);
            cp16(bufb + 1*STG_B + so, gAl + ge);
            cp16(bufb + 2*STG_B + so, gBh + ge);
            cp16(bufb + 3*STG_B + so, gBl + ge);
        }
        cp_commit();
    }

    for (int c = 0; c < nch; c++) {
        cp_wait<NSTAGES-2>();
        __syncthreads();
        // prefetch chunk c+NSTAGES-1 into the stage computed at iter c-1
        if (c + NSTAGES-1 < nch) {
            int cn = c + NSTAGES-1;
            uint32_t bufb = sb + (cn % NSTAGES) * STAGE_B;
            int koff = cn << 5;
            #pragma unroll
            for (int j = 0; j < 2; j++) {
                int u = lu0 + j;
                uint32_t so = swz64(lr, u);
                int ge = koff + u * 8;
                cp16(bufb + 0*STG_B + so, gAh + ge);
                cp16(bufb + 1*STG_B + so, gAl + ge);
                cp16(bufb + 2*STG_B + so, gBh + ge);
                cp16(bufb + 3*STG_B + so, gBl + ge);
            }
        }
        cp_commit();   // always commit (possibly-empty group keeps drain accounting exact)

        uint32_t base = sb + (c % NSTAGES) * STAGE_B;
        uint32_t aH = base, aL = base + STG_B, bH = base + 2*STG_B, bL = base + 3*STG_B;

        #pragma unroll
        for (int kk = 0; kk < 2; kk++) {
            uint32_t ah[2][4], al[2][4], bb[4][4];
            uint32_t offA[2], offB[4];
            #pragma unroll
            for (int t2 = 0; t2 < 2; t2++) {
                int r = wm + t2*16 + m_off;
                offA[t2] = swz64(r, kk*2 + a_ku);
                LDSM4(ah[t2][0], ah[t2][1], ah[t2][2], ah[t2][3], aH + offA[t2]);
                LDSM4(al[t2][0], al[t2][1], al[t2][2], al[t2][3], aL + offA[t2]);
            }
            #pragma unroll
            for (int p = 0; p < 4; p++) {
                int r = wn + p*16 + n_off;
                offB[p] = swz64(r, kk*2 + b_ku);
                LDSM4(bb[p][0], bb[p][1], bb[p][2], bb[p][3], bH + offB[p]);
            }
            // pass 1: Ahi*Bhi  + pass 2: Alo*Bhi
            #pragma unroll
            for (int t2 = 0; t2 < 2; t2++)
                #pragma unroll
                for (int p = 0; p < 4; p++) {
                    MMA16816(acc[t2][2*p],   ah[t2], bb[p][0], bb[p][1]);
                    MMA16816(acc[t2][2*p+1], ah[t2], bb[p][2], bb[p][3]);
                    MMA16816(acc[t2][2*p],   al[t2], bb[p][0], bb[p][1]);
                    MMA16816(acc[t2][2*p+1], al[t2], bb[p][2], bb[p][3]);
                }
            // pass 3: Ahi*Blo
            #pragma unroll
            for (int p = 0; p < 4; p++)
                LDSM4(bb[p][0], bb[p][1], bb[p][2], bb[p][3], bL + offB[p]);
            #pragma unroll
            for (int t2 = 0; t2 < 2; t2++)
                #pragma unroll
                for (int p = 0; p < 4; p++) {
                    MMA16816(acc[t2][2*p],   ah[t2], bb[p][0], bb[p][1]);
                    MMA16816(acc[t2][2*p+1], ah[t2], bb[p][2], bb[p][3]);
                }
        }
    }

    // ---------------- epilogue: fragment -> global ----------------
    #pragma unroll
    for (int t2 = 0; t2 < 2; t2++) {
        int row0 = mrow + wm + t2*16 + (lane >> 2);
        #pragma unroll
        for (int p8 = 0; p8 < 8; p8++) {
            int col = ncol + wn + p8*8 + (lane & 3)*2;
            #pragma unroll
            for (int half = 0; half < 2; half++) {
                int row = row0 + half*8;
                float v0 = acc[t2][p8][half*2 + 0];
                float v1 = acc[t2][p8][half*2 + 1];
                if (MODE == 0) {
                    int b = row >> 12, s = row & 4095;
                    int hh = col >> 6, dd = col & 63;
                    *(float2*)&Cf[(((size_t)b*HH + hh)*SS + s)*64 + dd] = make_float2(v0, v1);
                } else if (MODE == 1) {
                    float2* pp = (float2*)&Cf[(size_t)row*N + col];
                    float2 t = *pp; t.x += v0; t.y += v1; *pp = t;
                } else if (MODE == 2) {
                    float y0 = gelu_f(v0 + bias[col]);
                    float y1 = gelu_f(v1 + bias[col+1]);
                    __nv_bfloat16 h0 = __float2bfloat16(y0), h1 = __float2bfloat16(y1);
                    __nv_bfloat162 hh2; hh2.x = h0; hh2.y = h1;
                    __nv_bfloat162 ll2;
                    ll2.x = __float2bfloat16(y0 - __bfloat162float(h0));
                    ll2.y = __float2bfloat16(y1 - __bfloat162float(h1));
                    size_t o = (size_t)row*N + col;
                    *(__nv_bfloat162*)&Chi[o] = hh2;
                    *(__nv_bfloat162*)&Clo[o] = ll2;
                } else {
                    float2* pp = (float2*)&Cf[(size_t)row*N + col];
                    float2 t = *pp;
                    t.x += v0 + bias[col]; t.y += v1 + bias[col+1];
                    *pp = t;
                }
            }
        }
    }
}

// ---------------- row norms ----------------
__global__ void rownorm_kernel(const float* __restrict__ a, float* __restrict__ n, int rows) {
    int gw = (blockIdx.x * blockDim.x + threadIdx.x) >> 5;
    int lane = threadIdx.x & 31;
    if (gw >= rows) return;
    const float* r = a + (size_t)gw * 64;
    float v = r[lane]*r[lane] + r[lane+32]*r[lane+32];
    #pragma unroll
    for (int o = 16; o; o >>= 1) v += __shfl_xor_sync(~0u, v, o);
    if (!lane) n[gw] = sqrtf(v);
}

// ---------------- cosine dists ----------------
__global__ void dists_kernel(const float* __restrict__ q, const float* __restrict__ qn,
                             const float* __restrict__ means_l, const float* __restrict__ mn,
                             float* __restrict__ dists) {
    __shared__ float msm[64*65];
    __shared__ float qs[4*65];
    int bh = blockIdx.y;
    int h  = bh & 7;
    int s0 = blockIdx.x * 4;
    int tid = threadIdx.x;
    for (int e = tid; e < 4096; e += 256) {
        int c = e >> 6, d = e & 63;
        msm[c*65 + d] = means_l[(size_t)h*CC*DD + c*64 + d];
    }
    {
        int si = tid >> 6, d = tid & 63;
        qs[si*65 + d] = q[((size_t)bh*SS + s0 + si)*DD + d];
    }
    __syncthreads();
    int c = tid >> 2, si = tid & 3;
    int s = s0 + si;
    float dot = 0.f;
    #pragma unroll
    for (int d = 0; d < 64; d++) dot += qs[si*65 + d] * msm[c*65 + d];
    float denom = (qn[(size_t)bh*SS + s] + 1e-8f) * (mn[h*CC + c] + 1e-8f);
    dists[((size_t)bh*CC + c)*SS + s] = dot / denom;
}

// ---------------- top-64 per (b,h,c) ----------------
__global__ void topk_kernel(const float* __restrict__ dists, int* __restrict__ idx) {
    __shared__ float sv[SS];
    __shared__ float rv[256];
    __shared__ int   ri[256];
    int bid = blockIdx.x;
    int tid = threadIdx.x;
    const float* dr = dists + (size_t)bid * SS;
    for (int i = tid; i < SS; i += 256) sv[i] = dr[i];
    __syncthreads();
    for (int t = 0; t < WW; t++) {
        float bv = -INFINITY; int bi = SS;
        for (int i = tid; i < SS; i += 256) {
            float v = sv[i];
            if (v > bv || (v == bv && i < bi)) { bv = v; bi = i; }
        }
        rv[tid] = bv; ri[tid] = bi;
        __syncthreads();
        for (int st = 128; st > 0; st >>= 1) {
            if (tid < st) {
                if (rv[tid+st] > rv[tid] || (rv[tid+st] == rv[tid] && ri[tid+st] < ri[tid])) {
                    rv[tid] = rv[tid+st]; ri[tid] = ri[tid+st];
                }
            }
            __syncthreads();
        }
        if (tid == 0) { idx[bid*WW + t] = ri[0]; sv[ri[0]] = -INFINITY; }
        __syncthreads();
    }
}

// ---------------- bucketed attention + scatter-add ----------------
#define ATTN_SMEM_BYTES ((128 + 4*64*65) * 4)
__global__ void attn_kernel(const float* __restrict__ q, const float* __restrict__ k,
                            const float* __restrict__ v, const int* __restrict__ value,
                            const int* __restrict__ idx, float* __restrict__ oacc,
                            float* __restrict__ cnt) {
    extern __shared__ float smf[];
    int*   ids = (int*)smf;
    float* km  = smf + 64;
    float* qb  = smf + 128;
    float* kb  = qb + 64*65;
    float* vb  = kb + 64*65;
    float* sc  = vb + 64*65;
    int bid = blockIdx.x;
    int bh  = bid >> 6;
    int b   = bid >> 9;
    int tid = threadIdx.x;
    if (tid < 64) {
        int g = idx[bid*WW + tid];
        ids[tid] = g;
        km[tid] = (value[b*SS + g] != 0) ? 1.f : 0.f;
    }
    __syncthreads();
    for (int e = tid; e < 4096; e += 256) {
        int i = e >> 6, d = e & 63;
        size_t base = ((size_t)bh*SS + ids[i])*DD + d;
        qb[i*65 + d] = q[base];
        kb[i*65 + d] = k[base];
        vb[i*65 + d] = v[base];
    }
    __syncthreads();
    for (int e = tid; e < 4096; e += 256) {
        int i = e >> 6, j = e & 63;
        float s = 0.f;
        #pragma unroll
        for (int d = 0; d < 64; d++) s += qb[i*65 + d] * kb[j*65 + d];
        bool allowed = (ids[i] >= ids[j]) && (km[j] > 0.5f);
        sc[i*65 + j] = allowed ? s * 0.125f : -1e9f;
    }
    __syncthreads();
    {
        int w = tid >> 5, lane = tid & 31;
        for (int r = 0; r < 8; r++) {
            int i = w*8 + r;
            float v0 = sc[i*65 + lane], v1 = sc[i*65 + lane + 32];
            float m = fmaxf(v0, v1);
            #pragma unroll
            for (int o = 16; o; o >>= 1) m = fmaxf(m, __shfl_xor_sync(~0u, m, o));
            float e0 = expf(v0 - m), e1 = expf(v1 - m);
            float su = e0 + e1;
            #pragma unroll
            for (int o = 16; o; o >>= 1) su += __shfl_xor_sync(~0u, su, o);
            float inv = 1.f / su;
            sc[i*65 + lane]      = e0 * inv;
            sc[i*65 + lane + 32] = e1 * inv;
        }
    }
    __syncthreads();
    for (int e = tid; e < 4096; e += 256) {
        int i = e >> 6, d = e & 63;
        float s = 0.f;
        #pragma unroll
        for (int j = 0; j < 64; j++) s += sc[i*65 + j] * vb[j*65 + d];
        int g = ids[i];
        atomicAdd(&oacc[((size_t)bh*SS + g)*DD + d], s);
        if (d == 0) atomicAdd(&cnt[(size_t)bh*SS + g], 1.f);
    }
}

// ---------------- scatter-mean finalize -> bf16 hi/lo (B,S,E) ----------------
__global__ void finalize_kernel(const float* __restrict__ oacc, const float* __restrict__ cnt,
                                __nv_bfloat16* __restrict__ ahi, __nv_bfloat16* __restrict__ alo) {
    int row = blockIdx.x;
    int b = row >> 12, s = row & 4095;
    for (int e = threadIdx.x; e < EE; e += blockDim.x) {
        int hh = e >> 6, d = e & 63;
        int bh = b*HH + hh;
        float c = cnt[(size_t)bh*SS + s];
        float v = oacc[((size_t)bh*SS + s)*DD + d] / fmaxf(c, 1.f);
        __nv_bfloat16 h = __float2bfloat16(v);
        ahi[(size_t)row*EE + e] = h;
        alo[(size_t)row*EE + e] = __float2bfloat16(v - __bfloat162float(h));
    }
}

// ---------------- logit head ----------------
__global__ void head_kernel(const float* __restrict__ x, const float* __restrict__ hw,
                            float* __restrict__ out) {
    int row = blockIdx.x;
    int w = threadIdx.x >> 5, lane = threadIdx.x & 31;
    const float* xr = x + (size_t)row * EE;
    const float* wr = hw + (size_t)w * EE;
    float s = 0.f;
    for (int i = lane; i < EE; i += 32) s += xr[i] * wr[i];
    #pragma unroll
    for (int o = 16; o; o >>= 1) s += __shfl_xor_sync(~0u, s, o);
    if (!lane) out[(size_t)row*NVOC + w] = s;
}

// ---------------- host orchestration ----------------
extern "C" void kernel_launch(void* const* d_in, const int* in_sizes, int n_in,
                              void* d_out, int out_size) {
    const int*   value = (const int*)  d_in[0];
    const int*   depth = (const int*)  d_in[1];
    const int*   pos   = (const int*)  d_in[2];
    const float* sos   = (const float*)d_in[3];
    const float* tok   = (const float*)d_in[4];
    const float* dep   = (const float*)d_in[5];
    const float* pemb  = (const float*)d_in[6];
    const float* ln1s  = (const float*)d_in[7];
    const float* ln1b  = (const float*)d_in[8];
    const float* Wq    = (const float*)d_in[9];
    const float* Wk    = (const float*)d_in[10];
    const float* Wv    = (const float*)d_in[11];
    const float* Wo    = (const float*)d_in[12];
    const float* means = (const float*)d_in[13];
    const float* ln2s  = (const float*)d_in[14];
    const float* ln2b  = (const float*)d_in[15];
    const float* W1    = (const float*)d_in[16];
    const float* b1    = (const float*)d_in[17];
    const float* W2    = (const float*)d_in[18];
    const float* b2    = (const float*)d_in[19];
    const float* hw    = (const float*)d_in[20];
    float* out = (float*)d_out;

    float* base = nullptr;
    cudaGetSymbolAddress((void**)&base, g_buf);
    int* gidx = nullptr;
    cudaGetSymbolAddress((void**)&gidx, g_idx);
    __nv_bfloat16* wt = nullptr;
    cudaGetSymbolAddress((void**)&wt, g_wt);
    __nv_bfloat16* wt_lo = wt + WT_TOT;

    float* x     = base;
    __nv_bfloat16* h_hi = (__nv_bfloat16*)(base + 1*BSE);
    __nv_bfloat16* h_lo = h_hi + BSE;
    float* q     = base + 2*BSE;
    float* k     = base + 3*BSE;
    float* v     = base + 4*BSE;
    float* dists = base + 5*BSE;
    float* oacc  = base + 6*BSE;
    __nv_bfloat16* ab_hi = (__nv_bfloat16*)(base + 7*BSE);
    __nv_bfloat16* ab_lo = ab_hi + BSE;
    __nv_bfloat16* ff_hi = (__nv_bfloat16*)(base + 8*BSE);
    __nv_bfloat16* ff_lo = ff_hi + (size_t)BS*FF;
    float* qn    = base + 12*BSE;
    float* mn    = qn + BHS;
    float* cnt   = mn + 512;

    cudaFuncSetAttribute(attn_kernel, cudaFuncAttributeMaxDynamicSharedMemorySize, ATTN_SMEM_BYTES);
    cudaFuncSetAttribute(gemm_mma<0>, cudaFuncAttributeMaxDynamicSharedMemorySize, GT_SMEM);
    cudaFuncSetAttribute(gemm_mma<1>, cudaFuncAttributeMaxDynamicSharedMemorySize, GT_SMEM);
    cudaFuncSetAttribute(gemm_mma<2>, cudaFuncAttributeMaxDynamicSharedMemorySize, GT_SMEM);
    cudaFuncSetAttribute(gemm_mma<3>, cudaFuncAttributeMaxDynamicSharedMemorySize, GT_SMEM);

    // launch 1: all weight transposes (single kernel)
    wtrans_all<<<LL*3072, dim3(32,8)>>>(Wq, Wk, Wv, Wo, W1, W2, wt, wt_lo);

    // launch 2
    embed_kernel<<<BS, 256>>>(value, depth, pos, sos, tok, dep, pemb, x);

    const int M = BS;
    dim3 g512(512/128, M/128);
    dim3 gFF(FF/128, M/128);

    for (int l = 0; l < LL; l++) {
        size_t lb = (size_t)l * WT_LAYER;
        const __nv_bfloat16* wqt = wt + lb,           *wqtl = wt_lo + lb;
        const __nv_bfloat16* wkt = wt + lb + 262144,  *wktl = wt_lo + lb + 262144;
        const __nv_bfloat16* wvt = wt + lb + 524288,  *wvtl = wt_lo + lb + 524288;
        const __nv_bfloat16* wot = wt + lb + 786432,  *wotl = wt_lo + lb + 786432;
        const __nv_bfloat16* w1t = wt + lb + 1048576, *w1tl = wt_lo + lb + 1048576;
        const __nv_bfloat16* w2t = wt + lb + 2097152, *w2tl = wt_lo + lb + 2097152;
        const float* ml = means + (size_t)l*HH*CC*DD;

        // launches 3..6 on layer 0: ln, gemm Q, gemm K, gemm V (ncu -s 5 -c 1 profiles gemm V)
        ln_kernel<<<BS, 256>>>(x, ln1s + l*EE, ln1b + l*EE, h_hi, h_lo);
        gemm_mma<0><<<g512, 256, GT_SMEM>>>(h_hi, h_lo, wqt, wqtl, nullptr, q, nullptr, nullptr, M, 512, 512);
        gemm_mma<0><<<g512, 256, GT_SMEM>>>(h_hi, h_lo, wkt, wktl, nullptr, k, nullptr, nullptr, M, 512, 512);
        gemm_mma<0><<<g512, 256, GT_SMEM>>>(h_hi, h_lo, wvt, wvtl, nullptr, v, nullptr, nullptr, M, 512, 512);

        rownorm_kernel<<<(BHS*32)/256, 256>>>(q, qn, BHS);
        rownorm_kernel<<<(HH*CC*32)/256, 256>>>(ml, mn, HH*CC);
        dists_kernel<<<dim3(SS/4, BB*HH), 256>>>(q, qn, ml, mn, dists);
        topk_kernel<<<BB*HH*CC, 256>>>(dists, gidx);

        cudaMemsetAsync(oacc, 0, BSE * sizeof(float));
        cudaMemsetAsync(cnt, 0, BHS * sizeof(float));
        attn_kernel<<<BB*HH*CC, 256, ATTN_SMEM_BYTES>>>(q, k, v, value, gidx, oacc, cnt);
        finalize_kernel<<<BS, 256>>>(oacc, cnt, ab_hi, ab_lo);
        gemm_mma<1><<<g512, 256, GT_SMEM>>>(ab_hi, ab_lo, wot, wotl, nullptr, x, nullptr, nullptr, M, 512, 512);

        ln_kernel<<<BS, 256>>>(x, ln2s + l*EE, ln2b + l*EE, h_hi, h_lo);
        gemm_mma<2><<<gFF, 256, GT_SMEM>>>(h_hi, h_lo, w1t, w1tl, b1 + l*FF, nullptr, ff_hi, ff_lo, M, FF, 512);
        gemm_mma<3><<<g512, 256, GT_SMEM>>>(ff_hi, ff_lo, w2t, w2tl, b2 + l*EE, x, nullptr, nullptr, M, 512, FF);
    }

    head_kernel<<<BS, NVOC*32>>>(x, hw, out);
}

// round 6
// speedup vs baseline: 1.5490x; 1.5490x over previous
#include <cuda_runtime.h>
#include <cuda_bf16.h>
#include <cstdint>
#include <math.h>

#define BB 4
#define SS 4096
#define EE 512
#define HH 8
#define DD 64
#define CC 64
#define WW 64
#define LL 4
#define FF 2048
#define NVOC 17

#define BS (BB*SS)                 // 16384 rows
#define BSE ((size_t)BS*EE)        // 8388608
#define BHS (BB*HH*SS)             // 131072

// ---------------- device scratch (no allocations allowed) ----------------
__device__ float g_buf[12*BSE + BHS + 512 + BHS];
__device__ int   g_idx[BB*HH*CC*WW];
// transposed + bf16-split weights: per layer 4*(512*512) + 512*2048 + 2048*512 = 3145728
#define WT_LAYER 3145728
#define WT_TOT   ((size_t)LL*WT_LAYER)
__device__ __nv_bfloat16 g_wt[2*WT_TOT];   // [hi | lo]

// ================= PTX helpers =================
__device__ __forceinline__ uint32_t smem_u32(const void* p) {
    uint32_t a;
    asm("{ .reg .u64 t; cvta.to.shared.u64 t, %1; cvt.u32.u64 %0, t; }" : "=r"(a) : "l"(p));
    return a;
}
__device__ __forceinline__ void cp16(uint32_t saddr, const void* gptr) {
    asm volatile("cp.async.cg.shared.global [%0], [%1], 16;" :: "r"(saddr), "l"(gptr));
}
__device__ __forceinline__ void cp_commit() { asm volatile("cp.async.commit_group;" ::: "memory"); }
template<int N> __device__ __forceinline__ void cp_wait() { asm volatile("cp.async.wait_group %0;" :: "n"(N) : "memory"); }

#define LDSM4(r0,r1,r2,r3,addr) \
    asm volatile("ldmatrix.sync.aligned.m8n8.x4.shared.b16 {%0,%1,%2,%3}, [%4];" \
        : "=r"(r0), "=r"(r1), "=r"(r2), "=r"(r3) : "r"(addr))

#define MMA16816(c, a, b0, b1) \
    asm volatile("mma.sync.aligned.m16n8k16.row.col.f32.bf16.bf16.f32 " \
        "{%0,%1,%2,%3}, {%4,%5,%6,%7}, {%8,%9}, {%0,%1,%2,%3};" \
        : "+f"((c)[0]), "+f"((c)[1]), "+f"((c)[2]), "+f"((c)[3]) \
        : "r"((a)[0]), "r"((a)[1]), "r"((a)[2]), "r"((a)[3]), "r"(b0), "r"(b1))

#define SMEM_SWIZZLE_128B(o) ((o) ^ (((o) >> 3) & 0x70))

// ---------------- embedding + shift-right ----------------
__global__ void embed_kernel(const int* __restrict__ value, const int* __restrict__ depth,
                             const int* __restrict__ pos, const float* __restrict__ sos,
                             const float* __restrict__ tok, const float* __restrict__ dep,
                             const float* __restrict__ pemb, float* __restrict__ x) {
    int row = blockIdx.x;
    int b = row >> 12, s = row & 4095;
    float* xr = x + (size_t)row * EE;
    if (s == 0) {
        for (int i = threadIdx.x; i < EE; i += blockDim.x) xr[i] = sos[i];
        return;
    }
    int sp = s - 1;
    int v  = value[b*SS + sp];
    int dp = depth[b*SS + sp];
    int p0 = pos[(b*SS + sp)*3 + 0];
    int p1 = pos[(b*SS + sp)*3 + 1];
    int p2 = pos[(b*SS + sp)*3 + 2];
    const float* t0 = tok + (size_t)v*EE;
    const float* d0 = dep + (size_t)dp*EE;
    const float* e0 = pemb + ((size_t)0*65 + p0)*EE;
    const float* e1 = pemb + ((size_t)1*65 + p1)*EE;
    const float* e2 = pemb + ((size_t)2*65 + p2)*EE;
    for (int i = threadIdx.x; i < EE; i += blockDim.x)
        xr[i] = t0[i] + d0[i] + e0[i] + e1[i] + e2[i];
}

// ---------------- layernorm -> bf16 hi/lo ----------------
__global__ void ln_kernel(const float* __restrict__ x, const float* __restrict__ sc,
                          const float* __restrict__ bi, __nv_bfloat16* __restrict__ ohi,
                          __nv_bfloat16* __restrict__ olo) {
    int row = blockIdx.x;
    const float* xr = x + (size_t)row * EE;
    __shared__ float red[256];
    int tid = threadIdx.x;
    float v0 = xr[tid], v1 = xr[tid + 256];
    red[tid] = v0 + v1;
    __syncthreads();
    for (int st = 128; st > 0; st >>= 1) { if (tid < st) red[tid] += red[tid + st]; __syncthreads(); }
    float mean = red[0] * (1.f/512.f);
    __syncthreads();
    float d0 = v0 - mean, d1 = v1 - mean;
    red[tid] = d0*d0 + d1*d1;
    __syncthreads();
    for (int st = 128; st > 0; st >>= 1) { if (tid < st) red[tid] += red[tid + st]; __syncthreads(); }
    float var = red[0] * (1.f/512.f);
    float r = rsqrtf(var + 1e-5f);
    float y0 = d0 * r * sc[tid]       + bi[tid];
    float y1 = d1 * r * sc[tid + 256] + bi[tid + 256];
    __nv_bfloat16 h0 = __float2bfloat16(y0);
    __nv_bfloat16 h1 = __float2bfloat16(y1);
    size_t base = (size_t)row * EE;
    ohi[base + tid]       = h0;
    ohi[base + tid + 256] = h1;
    olo[base + tid]       = __float2bfloat16(y0 - __bfloat162float(h0));
    olo[base + tid + 256] = __float2bfloat16(y1 - __bfloat162float(h1));
}

// ---------------- ALL weights transpose + bf16 split in ONE launch ----------------
__global__ void wtrans_all(const float* __restrict__ Wq, const float* __restrict__ Wk,
                           const float* __restrict__ Wv, const float* __restrict__ Wo,
                           const float* __restrict__ W1, const float* __restrict__ W2,
                           __nv_bfloat16* __restrict__ hi_base, __nv_bfloat16* __restrict__ lo_base) {
    __shared__ float t[32][33];
    int bid = blockIdx.x;
    int l = bid / 3072, r = bid % 3072;
    const float* W; int K, N, tile; size_t off;
    if (r < 1024) {
        int ty = r >> 8; tile = r & 255; K = 512; N = 512;
        const float* Ws = (ty == 0) ? Wq : (ty == 1) ? Wk : (ty == 2) ? Wv : Wo;
        W = Ws + (size_t)l*512*512;
        off = (size_t)l*WT_LAYER + (size_t)ty*262144;
    } else if (r < 2048) {
        tile = r - 1024; K = 512; N = 2048;
        W = W1 + (size_t)l*512*2048;
        off = (size_t)l*WT_LAYER + 1048576;
    } else {
        tile = r - 2048; K = 2048; N = 512;
        W = W2 + (size_t)l*2048*512;
        off = (size_t)l*WT_LAYER + 2097152;
    }
    __nv_bfloat16* hi = hi_base + off;
    __nv_bfloat16* lo = lo_base + off;
    int tilesN = N >> 5;
    int n0 = (tile % tilesN) * 32, k0 = (tile / tilesN) * 32;
    for (int i = threadIdx.y; i < 32; i += 8)
        t[i][threadIdx.x] = W[(size_t)(k0 + i) * N + n0 + threadIdx.x];
    __syncthreads();
    for (int i = threadIdx.y; i < 32; i += 8) {
        int n = n0 + i, k = k0 + threadIdx.x;
        float v = t[threadIdx.x][i];
        __nv_bfloat16 h = __float2bfloat16(v);
        hi[(size_t)n*K + k] = h;
        lo[(size_t)n*K + k] = __float2bfloat16(v - __bfloat162float(h));
    }
}

// ---------------- HMMA GEMM: C[M,N] = A[M,K] @ B^T (B stored [N,K]) ----------------
// bf16x3: D = Ahi*Bhi + Alo*Bhi + Ahi*Blo, fp32 accumulate.
// Round-4 structure (K-chunk 64, 2-stage, prefetch-then-wait) + pass-separated MMA
// scheduling (16-MMA RAW distance on accumulators).
// MODE: 0 = splithead fp32 (QKV)   1 = resid fp32 (Wo)
//       2 = bias+gelu -> bf16 hi/lo (W1)   3 = bias+resid fp32 (W2)
#define CHB 16384                   // one array chunk: 128 rows * 128 B
#define BUFB (4*CHB)                // Ahi|Alo|Bhi|Blo
#define GT_SMEM (2*BUFB)            // 131072 (double buffered)

__device__ __forceinline__ float gelu_f(float x) {
    float x3 = x * x * x;
    return 0.5f * x * (1.0f + tanhf(0.7978845608028654f * (x + 0.044715f * x3)));
}

template<int MODE>
__global__ void __launch_bounds__(256) gemm_mma(
    const __nv_bfloat16* __restrict__ Ahi, const __nv_bfloat16* __restrict__ Alo,
    const __nv_bfloat16* __restrict__ Bhi, const __nv_bfloat16* __restrict__ Blo,
    const float* __restrict__ bias, float* __restrict__ Cf,
    __nv_bfloat16* __restrict__ Chi, __nv_bfloat16* __restrict__ Clo,
    int M, int N, int K)
{
    extern __shared__ char sm[];
    uint32_t sb = smem_u32(sm);
    int tid = threadIdx.x, wid = tid >> 5, lane = tid & 31;
    int mrow = blockIdx.y * 128, ncol = blockIdx.x * 128;
    int wm = (wid >> 1) * 32;       // 4 m-warps
    int wn = (wid & 1) * 64;        // 2 n-warps

    // cp.async loader assignment: thread -> (row, four 16B units)
    int lr = tid >> 1;
    int lu0 = (tid & 1) * 4;
    const __nv_bfloat16* gAh = Ahi + (size_t)(mrow + lr) * K;
    const __nv_bfloat16* gAl = Alo + (size_t)(mrow + lr) * K;
    const __nv_bfloat16* gBh = Bhi + (size_t)(ncol + lr) * K;
    const __nv_bfloat16* gBl = Blo + (size_t)(ncol + lr) * K;

    int nch = K >> 6;

    // fragment address components
    const int m_off = ((lane >> 3) & 1) * 8 + (lane & 7);
    const int a_ku  = (lane >> 4);
    const int n_off = ((lane >> 4) << 3) + (lane & 7);
    const int b_ku  = ((lane >> 3) & 1);

    float acc[2][8][4] = {};

    // prologue: load chunk 0
    {
        uint32_t bufb = sb;
        #pragma unroll
        for (int j = 0; j < 4; j++) {
            int u = lu0 + j;
            uint32_t so = SMEM_SWIZZLE_128B(lr*128 + (u << 4));
            int ge = u * 8;
            cp16(bufb + 0*CHB + so, gAh + ge);
            cp16(bufb + 1*CHB + so, gAl + ge);
            cp16(bufb + 2*CHB + so, gBh + ge);
            cp16(bufb + 3*CHB + so, gBl + ge);
        }
        cp_commit();
    }

    for (int c = 0; c < nch; c++) {
        if (c + 1 < nch) {
            uint32_t bufb = sb + ((c + 1) & 1) * BUFB;
            int koff = (c + 1) << 6;
            #pragma unroll
            for (int j = 0; j < 4; j++) {
                int u = lu0 + j;
                uint32_t so = SMEM_SWIZZLE_128B(lr*128 + (u << 4));
                int ge = koff + u * 8;
                cp16(bufb + 0*CHB + so, gAh + ge);
                cp16(bufb + 1*CHB + so, gAl + ge);
                cp16(bufb + 2*CHB + so, gBh + ge);
                cp16(bufb + 3*CHB + so, gBl + ge);
            }
            cp_commit();
            cp_wait<1>();
        } else {
            cp_wait<0>();
        }
        __syncthreads();

        uint32_t base = sb + (c & 1) * BUFB;
        uint32_t aH = base, aL = base + CHB, bH = base + 2*CHB, bL = base + 3*CHB;

        #pragma unroll
        for (int kk = 0; kk < 4; kk++) {
            uint32_t ah[2][4], al[2][4], bb[4][4];
            uint32_t offA[2], offB[4];
            #pragma unroll
            for (int t2 = 0; t2 < 2; t2++) {
                int r = wm + t2*16 + m_off;
                offA[t2] = (uint32_t)SMEM_SWIZZLE_128B(r*128 + ((kk*2 + a_ku) << 4));
                LDSM4(ah[t2][0], ah[t2][1], ah[t2][2], ah[t2][3], aH + offA[t2]);
                LDSM4(al[t2][0], al[t2][1], al[t2][2], al[t2][3], aL + offA[t2]);
            }
            #pragma unroll
            for (int p = 0; p < 4; p++) {
                int r = wn + p*16 + n_off;
                offB[p] = (uint32_t)SMEM_SWIZZLE_128B(r*128 + ((kk*2 + b_ku) << 4));
                LDSM4(bb[p][0], bb[p][1], bb[p][2], bb[p][3], bH + offB[p]);
            }
            // pass 1: Ahi*Bhi — 16 distinct accumulators, no RAW inside the pass
            #pragma unroll
            for (int t2 = 0; t2 < 2; t2++)
                #pragma unroll
                for (int p = 0; p < 4; p++) {
                    MMA16816(acc[t2][2*p],   ah[t2], bb[p][0], bb[p][1]);
                    MMA16816(acc[t2][2*p+1], ah[t2], bb[p][2], bb[p][3]);
                }
            // pass 2: Alo*Bhi — RAW distance 16 MMAs from pass 1
            #pragma unroll
            for (int t2 = 0; t2 < 2; t2++)
                #pragma unroll
                for (int p = 0; p < 4; p++) {
                    MMA16816(acc[t2][2*p],   al[t2], bb[p][0], bb[p][1]);
                    MMA16816(acc[t2][2*p+1], al[t2], bb[p][2], bb[p][3]);
                }
            // pass 3: Ahi*Blo — RAW distance 16 MMAs from pass 2
            #pragma unroll
            for (int p = 0; p < 4; p++)
                LDSM4(bb[p][0], bb[p][1], bb[p][2], bb[p][3], bL + offB[p]);
            #pragma unroll
            for (int t2 = 0; t2 < 2; t2++)
                #pragma unroll
                for (int p = 0; p < 4; p++) {
                    MMA16816(acc[t2][2*p],   ah[t2], bb[p][0], bb[p][1]);
                    MMA16816(acc[t2][2*p+1], ah[t2], bb[p][2], bb[p][3]);
                }
        }
        __syncthreads();
    }

    // ---------------- epilogue: fragment -> global ----------------
    #pragma unroll
    for (int t2 = 0; t2 < 2; t2++) {
        int row0 = mrow + wm + t2*16 + (lane >> 2);
        #pragma unroll
        for (int p8 = 0; p8 < 8; p8++) {
            int col = ncol + wn + p8*8 + (lane & 3)*2;
            #pragma unroll
            for (int half = 0; half < 2; half++) {
                int row = row0 + half*8;
                float v0 = acc[t2][p8][half*2 + 0];
                float v1 = acc[t2][p8][half*2 + 1];
                if (MODE == 0) {
                    int b = row >> 12, s = row & 4095;
                    int hh = col >> 6, dd = col & 63;
                    *(float2*)&Cf[(((size_t)b*HH + hh)*SS + s)*64 + dd] = make_float2(v0, v1);
                } else if (MODE == 1) {
                    float2* pp = (float2*)&Cf[(size_t)row*N + col];
                    float2 t = *pp; t.x += v0; t.y += v1; *pp = t;
                } else if (MODE == 2) {
                    float y0 = gelu_f(v0 + bias[col]);
                    float y1 = gelu_f(v1 + bias[col+1]);
                    __nv_bfloat16 h0 = __float2bfloat16(y0), h1 = __float2bfloat16(y1);
                    __nv_bfloat162 hh2; hh2.x = h0; hh2.y = h1;
                    __nv_bfloat162 ll2;
                    ll2.x = __float2bfloat16(y0 - __bfloat162float(h0));
                    ll2.y = __float2bfloat16(y1 - __bfloat162float(h1));
                    size_t o = (size_t)row*N + col;
                    *(__nv_bfloat162*)&Chi[o] = hh2;
                    *(__nv_bfloat162*)&Clo[o] = ll2;
                } else {
                    float2* pp = (float2*)&Cf[(size_t)row*N + col];
                    float2 t = *pp;
                    t.x += v0 + bias[col]; t.y += v1 + bias[col+1];
                    *pp = t;
                }
            }
        }
    }
}

// ---------------- row norms ----------------
__global__ void rownorm_kernel(const float* __restrict__ a, float* __restrict__ n, int rows) {
    int gw = (blockIdx.x * blockDim.x + threadIdx.x) >> 5;
    int lane = threadIdx.x & 31;
    if (gw >= rows) return;
    const float* r = a + (size_t)gw * 64;
    float v = r[lane]*r[lane] + r[lane+32]*r[lane+32];
    #pragma unroll
    for (int o = 16; o; o >>= 1) v += __shfl_xor_sync(~0u, v, o);
    if (!lane) n[gw] = sqrtf(v);
}

// ---------------- cosine dists ----------------
__global__ void dists_kernel(const float* __restrict__ q, const float* __restrict__ qn,
                             const float* __restrict__ means_l, const float* __restrict__ mn,
                             float* __restrict__ dists) {
    __shared__ float msm[64*65];
    __shared__ float qs[4*65];
    int bh = blockIdx.y;
    int h  = bh & 7;
    int s0 = blockIdx.x * 4;
    int tid = threadIdx.x;
    for (int e = tid; e < 4096; e += 256) {
        int c = e >> 6, d = e & 63;
        msm[c*65 + d] = means_l[(size_t)h*CC*DD + c*64 + d];
    }
    {
        int si = tid >> 6, d = tid & 63;
        qs[si*65 + d] = q[((size_t)bh*SS + s0 + si)*DD + d];
    }
    __syncthreads();
    int c = tid >> 2, si = tid & 3;
    int s = s0 + si;
    float dot = 0.f;
    #pragma unroll
    for (int d = 0; d < 64; d++) dot += qs[si*65 + d] * msm[c*65 + d];
    float denom = (qn[(size_t)bh*SS + s] + 1e-8f) * (mn[h*CC + c] + 1e-8f);
    dists[((size_t)bh*CC + c)*SS + s] = dot / denom;
}

// ---------------- top-64 per (b,h,c) ----------------
__global__ void topk_kernel(const float* __restrict__ dists, int* __restrict__ idx) {
    __shared__ float sv[SS];
    __shared__ float rv[256];
    __shared__ int   ri[256];
    int bid = blockIdx.x;
    int tid = threadIdx.x;
    const float* dr = dists + (size_t)bid * SS;
    for (int i = tid; i < SS; i += 256) sv[i] = dr[i];
    __syncthreads();
    for (int t = 0; t < WW; t++) {
        float bv = -INFINITY; int bi = SS;
        for (int i = tid; i < SS; i += 256) {
            float v = sv[i];
            if (v > bv || (v == bv && i < bi)) { bv = v; bi = i; }
        }
        rv[tid] = bv; ri[tid] = bi;
        __syncthreads();
        for (int st = 128; st > 0; st >>= 1) {
            if (tid < st) {
                if (rv[tid+st] > rv[tid] || (rv[tid+st] == rv[tid] && ri[tid+st] < ri[tid])) {
                    rv[tid] = rv[tid+st]; ri[tid] = ri[tid+st];
                }
            }
            __syncthreads();
        }
        if (tid == 0) { idx[bid*WW + t] = ri[0]; sv[ri[0]] = -INFINITY; }
        __syncthreads();
    }
}

// ---------------- bucketed attention + scatter-add ----------------
#define ATTN_SMEM_BYTES ((128 + 4*64*65) * 4)
__global__ void attn_kernel(const float* __restrict__ q, const float* __restrict__ k,
                            const float* __restrict__ v, const int* __restrict__ value,
                            const int* __restrict__ idx, float* __restrict__ oacc,
                            float* __restrict__ cnt) {
    extern __shared__ float smf[];
    int*   ids = (int*)smf;
    float* km  = smf + 64;
    float* qb  = smf + 128;
    float* kb  = qb + 64*65;
    float* vb  = kb + 64*65;
    float* sc  = vb + 64*65;
    int bid = blockIdx.x;
    int bh  = bid >> 6;
    int b   = bid >> 9;
    int tid = threadIdx.x;
    if (tid < 64) {
        int g = idx[bid*WW + tid];
        ids[tid] = g;
        km[tid] = (value[b*SS + g] != 0) ? 1.f : 0.f;
    }
    __syncthreads();
    for (int e = tid; e < 4096; e += 256) {
        int i = e >> 6, d = e & 63;
        size_t base = ((size_t)bh*SS + ids[i])*DD + d;
        qb[i*65 + d] = q[base];
        kb[i*65 + d] = k[base];
        vb[i*65 + d] = v[base];
    }
    __syncthreads();
    for (int e = tid; e < 4096; e += 256) {
        int i = e >> 6, j = e & 63;
        float s = 0.f;
        #pragma unroll
        for (int d = 0; d < 64; d++) s += qb[i*65 + d] * kb[j*65 + d];
        bool allowed = (ids[i] >= ids[j]) && (km[j] > 0.5f);
        sc[i*65 + j] = allowed ? s * 0.125f : -1e9f;
    }
    __syncthreads();
    {
        int w = tid >> 5, lane = tid & 31;
        for (int r = 0; r < 8; r++) {
            int i = w*8 + r;
            float v0 = sc[i*65 + lane], v1 = sc[i*65 + lane + 32];
            float m = fmaxf(v0, v1);
            #pragma unroll
            for (int o = 16; o; o >>= 1) m = fmaxf(m, __shfl_xor_sync(~0u, m, o));
            float e0 = expf(v0 - m), e1 = expf(v1 - m);
            float su = e0 + e1;
            #pragma unroll
            for (int o = 16; o; o >>= 1) su += __shfl_xor_sync(~0u, su, o);
            float inv = 1.f / su;
            sc[i*65 + lane]      = e0 * inv;
            sc[i*65 + lane + 32] = e1 * inv;
        }
    }
    __syncthreads();
    for (int e = tid; e < 4096; e += 256) {
        int i = e >> 6, d = e & 63;
        float s = 0.f;
        #pragma unroll
        for (int j = 0; j < 64; j++) s += sc[i*65 + j] * vb[j*65 + d];
        int g = ids[i];
        atomicAdd(&oacc[((size_t)bh*SS + g)*DD + d], s);
        if (d == 0) atomicAdd(&cnt[(size_t)bh*SS + g], 1.f);
    }
}

// ---------------- scatter-mean finalize -> bf16 hi/lo (B,S,E) ----------------
__global__ void finalize_kernel(const float* __restrict__ oacc, const float* __restrict__ cnt,
                                __nv_bfloat16* __restrict__ ahi, __nv_bfloat16* __restrict__ alo) {
    int row = blockIdx.x;
    int b = row >> 12, s = row & 4095;
    for (int e = threadIdx.x; e < EE; e += blockDim.x) {
        int hh = e >> 6, d = e & 63;
        int bh = b*HH + hh;
        float c = cnt[(size_t)bh*SS + s];
        float v = oacc[((size_t)bh*SS + s)*DD + d] / fmaxf(c, 1.f);
        __nv_bfloat16 h = __float2bfloat16(v);
        ahi[(size_t)row*EE + e] = h;
        alo[(size_t)row*EE + e] = __float2bfloat16(v - __bfloat162float(h));
    }
}

// ---------------- logit head ----------------
__global__ void head_kernel(const float* __restrict__ x, const float* __restrict__ hw,
                            float* __restrict__ out) {
    int row = blockIdx.x;
    int w = threadIdx.x >> 5, lane = threadIdx.x & 31;
    const float* xr = x + (size_t)row * EE;
    const float* wr = hw + (size_t)w * EE;
    float s = 0.f;
    for (int i = lane; i < EE; i += 32) s += xr[i] * wr[i];
    #pragma unroll
    for (int o = 16; o; o >>= 1) s += __shfl_xor_sync(~0u, s, o);
    if (!lane) out[(size_t)row*NVOC + w] = s;
}

// ---------------- host orchestration ----------------
extern "C" void kernel_launch(void* const* d_in, const int* in_sizes, int n_in,
                              void* d_out, int out_size) {
    const int*   value = (const int*)  d_in[0];
    const int*   depth = (const int*)  d_in[1];
    const int*   pos   = (const int*)  d_in[2];
    const float* sos   = (const float*)d_in[3];
    const float* tok   = (const float*)d_in[4];
    const float* dep   = (const float*)d_in[5];
    const float* pemb  = (const float*)d_in[6];
    const float* ln1s  = (const float*)d_in[7];
    const float* ln1b  = (const float*)d_in[8];
    const float* Wq    = (const float*)d_in[9];
    const float* Wk    = (const float*)d_in[10];
    const float* Wv    = (const float*)d_in[11];
    const float* Wo    = (const float*)d_in[12];
    const float* means = (const float*)d_in[13];
    const float* ln2s  = (const float*)d_in[14];
    const float* ln2b  = (const float*)d_in[15];
    const float* W1    = (const float*)d_in[16];
    const float* b1    = (const float*)d_in[17];
    const float* W2    = (const float*)d_in[18];
    const float* b2    = (const float*)d_in[19];
    const float* hw    = (const float*)d_in[20];
    float* out = (float*)d_out;

    float* base = nullptr;
    cudaGetSymbolAddress((void**)&base, g_buf);
    int* gidx = nullptr;
    cudaGetSymbolAddress((void**)&gidx, g_idx);
    __nv_bfloat16* wt = nullptr;
    cudaGetSymbolAddress((void**)&wt, g_wt);
    __nv_bfloat16* wt_lo = wt + WT_TOT;

    float* x     = base;
    __nv_bfloat16* h_hi = (__nv_bfloat16*)(base + 1*BSE);
    __nv_bfloat16* h_lo = h_hi + BSE;
    float* q     = base + 2*BSE;
    float* k     = base + 3*BSE;
    float* v     = base + 4*BSE;
    float* dists = base + 5*BSE;
    float* oacc  = base + 6*BSE;
    __nv_bfloat16* ab_hi = (__nv_bfloat16*)(base + 7*BSE);
    __nv_bfloat16* ab_lo = ab_hi + BSE;
    __nv_bfloat16* ff_hi = (__nv_bfloat16*)(base + 8*BSE);
    __nv_bfloat16* ff_lo = ff_hi + (size_t)BS*FF;
    float* qn    = base + 12*BSE;
    float* mn    = qn + BHS;
    float* cnt   = mn + 512;

    cudaFuncSetAttribute(attn_kernel, cudaFuncAttributeMaxDynamicSharedMemorySize, ATTN_SMEM_BYTES);
    cudaFuncSetAttribute(gemm_mma<0>, cudaFuncAttributeMaxDynamicSharedMemorySize, GT_SMEM);
    cudaFuncSetAttribute(gemm_mma<1>, cudaFuncAttributeMaxDynamicSharedMemorySize, GT_SMEM);
    cudaFuncSetAttribute(gemm_mma<2>, cudaFuncAttributeMaxDynamicSharedMemorySize, GT_SMEM);
    cudaFuncSetAttribute(gemm_mma<3>, cudaFuncAttributeMaxDynamicSharedMemorySize, GT_SMEM);

    // launch 1: all weight transposes (single kernel)
    wtrans_all<<<LL*3072, dim3(32,8)>>>(Wq, Wk, Wv, Wo, W1, W2, wt, wt_lo);

    // launch 2
    embed_kernel<<<BS, 256>>>(value, depth, pos, sos, tok, dep, pemb, x);

    const int M = BS;
    dim3 g512(512/128, M/128);
    dim3 gFF(FF/128, M/128);

    for (int l = 0; l < LL; l++) {
        size_t lb = (size_t)l * WT_LAYER;
        const __nv_bfloat16* wqt = wt + lb,           *wqtl = wt_lo + lb;
        const __nv_bfloat16* wkt = wt + lb + 262144,  *wktl = wt_lo + lb + 262144;
        const __nv_bfloat16* wvt = wt + lb + 524288,  *wvtl = wt_lo + lb + 524288;
        const __nv_bfloat16* wot = wt + lb + 786432,  *wotl = wt_lo + lb + 786432;
        const __nv_bfloat16* w1t = wt + lb + 1048576, *w1tl = wt_lo + lb + 1048576;
        const __nv_bfloat16* w2t = wt + lb + 2097152, *w2tl = wt_lo + lb + 2097152;
        const float* ml = means + (size_t)l*HH*CC*DD;

        ln_kernel<<<BS, 256>>>(x, ln1s + l*EE, ln1b + l*EE, h_hi, h_lo);
        gemm_mma<0><<<g512, 256, GT_SMEM>>>(h_hi, h_lo, wqt, wqtl, nullptr, q, nullptr, nullptr, M, 512, 512);
        gemm_mma<0><<<g512, 256, GT_SMEM>>>(h_hi, h_lo, wkt, wktl, nullptr, k, nullptr, nullptr, M, 512, 512);
        gemm_mma<0><<<g512, 256, GT_SMEM>>>(h_hi, h_lo, wvt, wvtl, nullptr, v, nullptr, nullptr, M, 512, 512);

        rownorm_kernel<<<(BHS*32)/256, 256>>>(q, qn, BHS);
        rownorm_kernel<<<(HH*CC*32)/256, 256>>>(ml, mn, HH*CC);
        dists_kernel<<<dim3(SS/4, BB*HH), 256>>>(q, qn, ml, mn, dists);
        topk_kernel<<<BB*HH*CC, 256>>>(dists, gidx);

        cudaMemsetAsync(oacc, 0, BSE * sizeof(float));
        cudaMemsetAsync(cnt, 0, BHS * sizeof(float));
        attn_kernel<<<BB*HH*CC, 256, ATTN_SMEM_BYTES>>>(q, k, v, value, gidx, oacc, cnt);
        finalize_kernel<<<BS, 256>>>(oacc, cnt, ab_hi, ab_lo);
        gemm_mma<1><<<g512, 256, GT_SMEM>>>(ab_hi, ab_lo, wot, wotl, nullptr, x, nullptr, nullptr, M, 512, 512);

        ln_kernel<<<BS, 256>>>(x, ln2s + l*EE, ln2b + l*EE, h_hi, h_lo);
        gemm_mma<2><<<gFF, 256, GT_SMEM>>>(h_hi, h_lo, w1t, w1tl, b1 + l*FF, nullptr, ff_hi, ff_lo, M, FF, 512);
        gemm_mma<3><<<g512, 256, GT_SMEM>>>(ff_hi, ff_lo, w2t, w2tl, b2 + l*EE, x, nullptr, nullptr, M, 512, FF);
    }

    head_kernel<<<BS, NVOC*32>>>(x, hw, out);
}

// round 11
// speedup vs baseline: 1.7338x; 1.1193x over previous
#include <cuda_runtime.h>
#include <cuda_bf16.h>
#include <cstdint>
#include <math.h>

#define BB 4
#define SS 4096
#define EE 512
#define HH 8
#define DD 64
#define CC 64
#define WW 64
#define LL 4
#define FF 2048
#define NVOC 17

#define BS (BB*SS)                 // 16384 rows
#define BSE ((size_t)BS*EE)        // 8388608
#define BHS (BB*HH*SS)             // 131072

// ---------------- device scratch (no allocations allowed) ----------------
__device__ float g_buf[12*BSE + BHS + 512 + BHS];
__device__ int   g_idx[BB*HH*CC*WW];
#define WT_LAYER 3145728
#define WT_TOT   ((size_t)LL*WT_LAYER)
__device__ __nv_bfloat16 g_wt[2*WT_TOT];   // [hi | lo]

// ================= PTX helpers =================
__device__ __forceinline__ uint32_t smem_u32(const void* p) {
    uint32_t a;
    asm("{ .reg .u64 t; cvta.to.shared.u64 t, %1; cvt.u32.u64 %0, t; }" : "=r"(a) : "l"(p));
    return a;
}
__device__ __forceinline__ void cp16(uint32_t saddr, const void* gptr) {
    asm volatile("cp.async.cg.shared.global [%0], [%1], 16;" :: "r"(saddr), "l"(gptr));
}
__device__ __forceinline__ void cp_commit() { asm volatile("cp.async.commit_group;" ::: "memory"); }
template<int N> __device__ __forceinline__ void cp_wait() { asm volatile("cp.async.wait_group %0;" :: "n"(N) : "memory"); }

#define LDSM4(r0,r1,r2,r3,addr) \
    asm volatile("ldmatrix.sync.aligned.m8n8.x4.shared.b16 {%0,%1,%2,%3}, [%4];" \
        : "=r"(r0), "=r"(r1), "=r"(r2), "=r"(r3) : "r"(addr))

#define MMA16816(c, a, b0, b1) \
    asm volatile("mma.sync.aligned.m16n8k16.row.col.f32.bf16.bf16.f32 " \
        "{%0,%1,%2,%3}, {%4,%5,%6,%7}, {%8,%9}, {%0,%1,%2,%3};" \
        : "+f"((c)[0]), "+f"((c)[1]), "+f"((c)[2]), "+f"((c)[3]) \
        : "r"((a)[0]), "r"((a)[1]), "r"((a)[2]), "r"((a)[3]), "r"(b0), "r"(b1))

// ---------------- embedding + shift-right ----------------
__global__ void embed_kernel(const int* __restrict__ value, const int* __restrict__ depth,
                             const int* __restrict__ pos, const float* __restrict__ sos,
                             const float* __restrict__ tok, const float* __restrict__ dep,
                             const float* __restrict__ pemb, float* __restrict__ x) {
    int row = blockIdx.x;
    int b = row >> 12, s = row & 4095;
    float* xr = x + (size_t)row * EE;
    if (s == 0) {
        for (int i = threadIdx.x; i < EE; i += blockDim.x) xr[i] = sos[i];
        return;
    }
    int sp = s - 1;
    int v  = value[b*SS + sp];
    int dp = depth[b*SS + sp];
    int p0 = pos[(b*SS + sp)*3 + 0];
    int p1 = pos[(b*SS + sp)*3 + 1];
    int p2 = pos[(b*SS + sp)*3 + 2];
    const float* t0 = tok + (size_t)v*EE;
    const float* d0 = dep + (size_t)dp*EE;
    const float* e0 = pemb + ((size_t)0*65 + p0)*EE;
    const float* e1 = pemb + ((size_t)1*65 + p1)*EE;
    const float* e2 = pemb + ((size_t)2*65 + p2)*EE;
    for (int i = threadIdx.x; i < EE; i += blockDim.x)
        xr[i] = t0[i] + d0[i] + e0[i] + e1[i] + e2[i];
}

// ---------------- layernorm -> bf16 hi/lo ----------------
__global__ void ln_kernel(const float* __restrict__ x, const float* __restrict__ sc,
                          const float* __restrict__ bi, __nv_bfloat16* __restrict__ ohi,
                          __nv_bfloat16* __restrict__ olo) {
    int row = blockIdx.x;
    const float* xr = x + (size_t)row * EE;
    __shared__ float red[256];
    int tid = threadIdx.x;
    float v0 = xr[tid], v1 = xr[tid + 256];
    red[tid] = v0 + v1;
    __syncthreads();
    for (int st = 128; st > 0; st >>= 1) { if (tid < st) red[tid] += red[tid + st]; __syncthreads(); }
    float mean = red[0] * (1.f/512.f);
    __syncthreads();
    float d0 = v0 - mean, d1 = v1 - mean;
    red[tid] = d0*d0 + d1*d1;
    __syncthreads();
    for (int st = 128; st > 0; st >>= 1) { if (tid < st) red[tid] += red[tid + st]; __syncthreads(); }
    float var = red[0] * (1.f/512.f);
    float r = rsqrtf(var + 1e-5f);
    float y0 = d0 * r * sc[tid]       + bi[tid];
    float y1 = d1 * r * sc[tid + 256] + bi[tid + 256];
    __nv_bfloat16 h0 = __float2bfloat16(y0);
    __nv_bfloat16 h1 = __float2bfloat16(y1);
    size_t base = (size_t)row * EE;
    ohi[base + tid]       = h0;
    ohi[base + tid + 256] = h1;
    olo[base + tid]       = __float2bfloat16(y0 - __bfloat162float(h0));
    olo[base + tid + 256] = __float2bfloat16(y1 - __bfloat162float(h1));
}

// ---------------- ALL weights transpose + bf16 split in ONE launch ----------------
__global__ void wtrans_all(const float* __restrict__ Wq, const float* __restrict__ Wk,
                           const float* __restrict__ Wv, const float* __restrict__ Wo,
                           const float* __restrict__ W1, const float* __restrict__ W2,
                           __nv_bfloat16* __restrict__ hi_base, __nv_bfloat16* __restrict__ lo_base) {
    __shared__ float t[32][33];
    int bid = blockIdx.x;
    int l = bid / 3072, r = bid % 3072;
    const float* W; int K, N, tile; size_t off;
    if (r < 1024) {
        int ty = r >> 8; tile = r & 255; K = 512; N = 512;
        const float* Ws = (ty == 0) ? Wq : (ty == 1) ? Wk : (ty == 2) ? Wv : Wo;
        W = Ws + (size_t)l*512*512;
        off = (size_t)l*WT_LAYER + (size_t)ty*262144;
    } else if (r < 2048) {
        tile = r - 1024; K = 512; N = 2048;
        W = W1 + (size_t)l*512*2048;
        off = (size_t)l*WT_LAYER + 1048576;
    } else {
        tile = r - 2048; K = 2048; N = 512;
        W = W2 + (size_t)l*2048*512;
        off = (size_t)l*WT_LAYER + 2097152;
    }
    __nv_bfloat16* hi = hi_base + off;
    __nv_bfloat16* lo = lo_base + off;
    int tilesN = N >> 5;
    int n0 = (tile % tilesN) * 32, k0 = (tile / tilesN) * 32;
    for (int i = threadIdx.y; i < 32; i += 8)
        t[i][threadIdx.x] = W[(size_t)(k0 + i) * N + n0 + threadIdx.x];
    __syncthreads();
    for (int i = threadIdx.y; i < 32; i += 8) {
        int n = n0 + i, k = k0 + threadIdx.x;
        float v = t[threadIdx.x][i];
        __nv_bfloat16 h = __float2bfloat16(v);
        hi[(size_t)n*K + k] = h;
        lo[(size_t)n*K + k] = __float2bfloat16(v - __bfloat162float(h));
    }
}

// ---------------- HMMA GEMM: C[M,N] = A[M,K] @ B^T (B stored [N,K]) ----------------
// bf16x3: D = Ahi*Bhi + Alo*Bhi + Ahi*Blo, fp32 accumulate.
// K-chunk 32 (64B rows), 2-stage, prefetch-then-wait, pass-separated MMA.
// 64 KB smem + <=128 regs -> 2 CTAs/SM.
// MODE: 0 = fused-QKV splithead fp32 (N=1536, which=col>>9)   1 = resid fp32 (Wo)
//       2 = bias+gelu -> bf16 hi/lo (W1)   3 = bias+resid fp32 (W2)
#define STG_B 8192                  // per-array stage: 128 rows * 64 B
#define STAGE_B (4*STG_B)           // Ahi|Alo|Bhi|Blo = 32 KB
#define GT_SMEM (2*STAGE_B)         // 65536 (double buffered)

__device__ __forceinline__ uint32_t swz64(int r, int u) {
    return (uint32_t)(r*64 + ((u ^ ((r >> 1) & 3)) << 4));
}

__device__ __forceinline__ float gelu_f(float x) {
    float x3 = x * x * x;
    return 0.5f * x * (1.0f + tanhf(0.7978845608028654f * (x + 0.044715f * x3)));
}

template<int MODE>
__global__ void __launch_bounds__(256, 2) gemm_mma(
    const __nv_bfloat16* __restrict__ Ahi, const __nv_bfloat16* __restrict__ Alo,
    const __nv_bfloat16* __restrict__ Bhi, const __nv_bfloat16* __restrict__ Blo,
    const float* __restrict__ bias, float* __restrict__ Cf,
    __nv_bfloat16* __restrict__ Chi, __nv_bfloat16* __restrict__ Clo,
    int M, int N, int K)
{
    extern __shared__ char sm[];
    uint32_t sb = smem_u32(sm);
    int tid = threadIdx.x, wid = tid >> 5, lane = tid & 31;
    int mrow = blockIdx.y * 128, ncol = blockIdx.x * 128;
    int wm = (wid >> 1) * 32;       // 4 m-warps
    int wn = (wid & 1) * 64;        // 2 n-warps

    // cp.async loader: thread -> (row, two 16B units) over 64B rows
    int lr = tid >> 1;
    int lu0 = (tid & 1) * 2;
    const __nv_bfloat16* gAh = Ahi + (size_t)(mrow + lr) * K;
    const __nv_bfloat16* gAl = Alo + (size_t)(mrow + lr) * K;
    const __nv_bfloat16* gBh = Bhi + (size_t)(ncol + lr) * K;
    const __nv_bfloat16* gBl = Blo + (size_t)(ncol + lr) * K;

    int nch = K >> 5;

    const int m_off = ((lane >> 3) & 1) * 8 + (lane & 7);
    const int a_ku  = (lane >> 4);
    const int n_off = ((lane >> 4) << 3) + (lane & 7);
    const int b_ku  = ((lane >> 3) & 1);

    float acc[2][8][4] = {};

    // prologue: load chunk 0
    {
        #pragma unroll
        for (int j = 0; j < 2; j++) {
            int u = lu0 + j;
            uint32_t so = swz64(lr, u);
            int ge = u * 8;
            cp16(sb + 0*STG_B + so, gAh + ge);
            cp16(sb + 1*STG_B + so, gAl + ge);
            cp16(sb + 2*STG_B + so, gBh + ge);
            cp16(sb + 3*STG_B + so, gBl + ge);
        }
        cp_commit();
    }

    for (int c = 0; c < nch; c++) {
        if (c + 1 < nch) {
            uint32_t bufb = sb + ((c + 1) & 1) * STAGE_B;
            int koff = (c + 1) << 5;
            #pragma unroll
            for (int j = 0; j < 2; j++) {
                int u = lu0 + j;
                uint32_t so = swz64(lr, u);
                int ge = koff + u * 8;
                cp16(bufb + 0*STG_B + so, gAh + ge);
                cp16(bufb + 1*STG_B + so, gAl + ge);
                cp16(bufb + 2*STG_B + so, gBh + ge);
                cp16(bufb + 3*STG_B + so, gBl + ge);
            }
            cp_commit();
            cp_wait<1>();
        } else {
            cp_wait<0>();
        }
        __syncthreads();

        uint32_t base = sb + (c & 1) * STAGE_B;
        uint32_t aH = base, aL = base + STG_B, bH = base + 2*STG_B, bL = base + 3*STG_B;

        #pragma unroll
        for (int kk = 0; kk < 2; kk++) {
            uint32_t ah[2][4], al[2][4], bb[4][4];
            uint32_t offA[2], offB[4];
            #pragma unroll
            for (int t2 = 0; t2 < 2; t2++) {
                int r = wm + t2*16 + m_off;
                offA[t2] = swz64(r, kk*2 + a_ku);
                LDSM4(ah[t2][0], ah[t2][1], ah[t2][2], ah[t2][3], aH + offA[t2]);
                LDSM4(al[t2][0], al[t2][1], al[t2][2], al[t2][3], aL + offA[t2]);
            }
            #pragma unroll
            for (int p = 0; p < 4; p++) {
                int r = wn + p*16 + n_off;
                offB[p] = swz64(r, kk*2 + b_ku);
                LDSM4(bb[p][0], bb[p][1], bb[p][2], bb[p][3], bH + offB[p]);
            }
            // pass 1: Ahi*Bhi
            #pragma unroll
            for (int t2 = 0; t2 < 2; t2++)
                #pragma unroll
                for (int p = 0; p < 4; p++) {
                    MMA16816(acc[t2][2*p],   ah[t2], bb[p][0], bb[p][1]);
                    MMA16816(acc[t2][2*p+1], ah[t2], bb[p][2], bb[p][3]);
                }
            // pass 2: Alo*Bhi
            #pragma unroll
            for (int t2 = 0; t2 < 2; t2++)
                #pragma unroll
                for (int p = 0; p < 4; p++) {
                    MMA16816(acc[t2][2*p],   al[t2], bb[p][0], bb[p][1]);
                    MMA16816(acc[t2][2*p+1], al[t2], bb[p][2], bb[p][3]);
                }
            // pass 3: Ahi*Blo
            #pragma unroll
            for (int p = 0; p < 4; p++)
                LDSM4(bb[p][0], bb[p][1], bb[p][2], bb[p][3], bL + offB[p]);
            #pragma unroll
            for (int t2 = 0; t2 < 2; t2++)
                #pragma unroll
                for (int p = 0; p < 4; p++) {
                    MMA16816(acc[t2][2*p],   ah[t2], bb[p][0], bb[p][1]);
                    MMA16816(acc[t2][2*p+1], ah[t2], bb[p][2], bb[p][3]);
                }
        }
        __syncthreads();
    }

    // ---------------- epilogue ----------------
    #pragma unroll
    for (int t2 = 0; t2 < 2; t2++) {
        int row0 = mrow + wm + t2*16 + (lane >> 2);
        #pragma unroll
        for (int p8 = 0; p8 < 8; p8++) {
            int col = ncol + wn + p8*8 + (lane & 3)*2;
            #pragma unroll
            for (int half = 0; half < 2; half++) {
                int row = row0 + half*8;
                float v0 = acc[t2][p8][half*2 + 0];
                float v1 = acc[t2][p8][half*2 + 1];
                if (MODE == 0) {
                    int which = col >> 9;         // 0=q,1=k,2=v
                    int c2 = col & 511;
                    int b = row >> 12, s = row & 4095;
                    int hh = c2 >> 6, dd = c2 & 63;
                    float* dst = Cf + (size_t)which*BSE;
                    *(float2*)&dst[(((size_t)b*HH + hh)*SS + s)*64 + dd] = make_float2(v0, v1);
                } else if (MODE == 1) {
                    float2* pp = (float2*)&Cf[(size_t)row*N + col];
                    float2 t = *pp; t.x += v0; t.y += v1; *pp = t;
                } else if (MODE == 2) {
                    float y0 = gelu_f(v0 + bias[col]);
                    float y1 = gelu_f(v1 + bias[col+1]);
                    __nv_bfloat16 h0 = __float2bfloat16(y0), h1 = __float2bfloat16(y1);
                    __nv_bfloat162 hh2; hh2.x = h0; hh2.y = h1;
                    __nv_bfloat162 ll2;
                    ll2.x = __float2bfloat16(y0 - __bfloat162float(h0));
                    ll2.y = __float2bfloat16(y1 - __bfloat162float(h1));
                    size_t o = (size_t)row*N + col;
                    *(__nv_bfloat162*)&Chi[o] = hh2;
                    *(__nv_bfloat162*)&Clo[o] = ll2;
                } else {
                    float2* pp = (float2*)&Cf[(size_t)row*N + col];
                    float2 t = *pp;
                    t.x += v0 + bias[col]; t.y += v1 + bias[col+1];
                    *pp = t;
                }
            }
        }
    }
}

// ---------------- row norms ----------------
__global__ void rownorm_kernel(const float* __restrict__ a, float* __restrict__ n, int rows) {
    int gw = (blockIdx.x * blockDim.x + threadIdx.x) >> 5;
    int lane = threadIdx.x & 31;
    if (gw >= rows) return;
    const float* r = a + (size_t)gw * 64;
    float v = r[lane]*r[lane] + r[lane+32]*r[lane+32];
    #pragma unroll
    for (int o = 16; o; o >>= 1) v += __shfl_xor_sync(~0u, v, o);
    if (!lane) n[gw] = sqrtf(v);
}

// ---------------- cosine dists ----------------
__global__ void dists_kernel(const float* __restrict__ q, const float* __restrict__ qn,
                             const float* __restrict__ means_l, const float* __restrict__ mn,
                             float* __restrict__ dists) {
    __shared__ float msm[64*65];
    __shared__ float qs[4*65];
    int bh = blockIdx.y;
    int h  = bh & 7;
    int s0 = blockIdx.x * 4;
    int tid = threadIdx.x;
    for (int e = tid; e < 4096; e += 256) {
        int c = e >> 6, d = e & 63;
        msm[c*65 + d] = means_l[(size_t)h*CC*DD + c*64 + d];
    }
    {
        int si = tid >> 6, d = tid & 63;
        qs[si*65 + d] = q[((size_t)bh*SS + s0 + si)*DD + d];
    }
    __syncthreads();
    int c = tid >> 2, si = tid & 3;
    int s = s0 + si;
    float dot = 0.f;
    #pragma unroll
    for (int d = 0; d < 64; d++) dot += qs[si*65 + d] * msm[c*65 + d];
    float denom = (qn[(size_t)bh*SS + s] + 1e-8f) * (mn[h*CC + c] + 1e-8f);
    dists[((size_t)bh*CC + c)*SS + s] = dot / denom;
}

// ---------------- top-64 per (b,h,c) ----------------
__global__ void topk_kernel(const float* __restrict__ dists, int* __restrict__ idx) {
    __shared__ float sv[SS];
    __shared__ float rv[256];
    __shared__ int   ri[256];
    int bid = blockIdx.x;
    int tid = threadIdx.x;
    const float* dr = dists + (size_t)bid * SS;
    for (int i = tid; i < SS; i += 256) sv[i] = dr[i];
    __syncthreads();
    for (int t = 0; t < WW; t++) {
        float bv = -INFINITY; int bi = SS;
        for (int i = tid; i < SS; i += 256) {
            float v = sv[i];
            if (v > bv || (v == bv && i < bi)) { bv = v; bi = i; }
        }
        rv[tid] = bv; ri[tid] = bi;
        __syncthreads();
        for (int st = 128; st > 0; st >>= 1) {
            if (tid < st) {
                if (rv[tid+st] > rv[tid] || (rv[tid+st] == rv[tid] && ri[tid+st] < ri[tid])) {
                    rv[tid] = rv[tid+st]; ri[tid] = ri[tid+st];
                }
            }
            __syncthreads();
        }
        if (tid == 0) { idx[bid*WW + t] = ri[0]; sv[ri[0]] = -INFINITY; }
        __syncthreads();
    }
}

// ---------------- bucketed attention + scatter-add ----------------
#define ATTN_SMEM_BYTES ((128 + 4*64*65) * 4)
__global__ void attn_kernel(const float* __restrict__ q, const float* __restrict__ k,
                            const float* __restrict__ v, const int* __restrict__ value,
                            const int* __restrict__ idx, float* __restrict__ oacc,
                            float* __restrict__ cnt) {
    extern __shared__ float smf[];
    int*   ids = (int*)smf;
    float* km  = smf + 64;
    float* qb  = smf + 128;
    float* kb  = qb + 64*65;
    float* vb  = kb + 64*65;
    float* sc  = vb + 64*65;
    int bid = blockIdx.x;
    int bh  = bid >> 6;
    int b   = bid >> 9;
    int tid = threadIdx.x;
    if (tid < 64) {
        int g = idx[bid*WW + tid];
        ids[tid] = g;
        km[tid] = (value[b*SS + g] != 0) ? 1.f : 0.f;
    }
    __syncthreads();
    for (int e = tid; e < 4096; e += 256) {
        int i = e >> 6, d = e & 63;
        size_t base = ((size_t)bh*SS + ids[i])*DD + d;
        qb[i*65 + d] = q[base];
        kb[i*65 + d] = k[base];
        vb[i*65 + d] = v[base];
    }
    __syncthreads();
    for (int e = tid; e < 4096; e += 256) {
        int i = e >> 6, j = e & 63;
        float s = 0.f;
        #pragma unroll
        for (int d = 0; d < 64; d++) s += qb[i*65 + d] * kb[j*65 + d];
        bool allowed = (ids[i] >= ids[j]) && (km[j] > 0.5f);
        sc[i*65 + j] = allowed ? s * 0.125f : -1e9f;
    }
    __syncthreads();
    {
        int w = tid >> 5, lane = tid & 31;
        for (int r = 0; r < 8; r++) {
            int i = w*8 + r;
            float v0 = sc[i*65 + lane], v1 = sc[i*65 + lane + 32];
            float m = fmaxf(v0, v1);
            #pragma unroll
            for (int o = 16; o; o >>= 1) m = fmaxf(m, __shfl_xor_sync(~0u, m, o));
            float e0 = expf(v0 - m), e1 = expf(v1 - m);
            float su = e0 + e1;
            #pragma unroll
            for (int o = 16; o; o >>= 1) su += __shfl_xor_sync(~0u, su, o);
            float inv = 1.f / su;
            sc[i*65 + lane]      = e0 * inv;
            sc[i*65 + lane + 32] = e1 * inv;
        }
    }
    __syncthreads();
    for (int e = tid; e < 4096; e += 256) {
        int i = e >> 6, d = e & 63;
        float s = 0.f;
        #pragma unroll
        for (int j = 0; j < 64; j++) s += sc[i*65 + j] * vb[j*65 + d];
        int g = ids[i];
        atomicAdd(&oacc[((size_t)bh*SS + g)*DD + d], s);
        if (d == 0) atomicAdd(&cnt[(size_t)bh*SS + g], 1.f);
    }
}

// ---------------- scatter-mean finalize -> bf16 hi/lo (B,S,E) ----------------
__global__ void finalize_kernel(const float* __restrict__ oacc, const float* __restrict__ cnt,
                                __nv_bfloat16* __restrict__ ahi, __nv_bfloat16* __restrict__ alo) {
    int row = blockIdx.x;
    int b = row >> 12, s = row & 4095;
    for (int e = threadIdx.x; e < EE; e += blockDim.x) {
        int hh = e >> 6, d = e & 63;
        int bh = b*HH + hh;
        float c = cnt[(size_t)bh*SS + s];
        float v = oacc[((size_t)bh*SS + s)*DD + d] / fmaxf(c, 1.f);
        __nv_bfloat16 h = __float2bfloat16(v);
        ahi[(size_t)row*EE + e] = h;
        alo[(size_t)row*EE + e] = __float2bfloat16(v - __bfloat162float(h));
    }
}

// ---------------- logit head ----------------
__global__ void head_kernel(const float* __restrict__ x, const float* __restrict__ hw,
                            float* __restrict__ out) {
    int row = blockIdx.x;
    int w = threadIdx.x >> 5, lane = threadIdx.x & 31;
    const float* xr = x + (size_t)row * EE;
    const float* wr = hw + (size_t)w * EE;
    float s = 0.f;
    for (int i = lane; i < EE; i += 32) s += xr[i] * wr[i];
    #pragma unroll
    for (int o = 16; o; o >>= 1) s += __shfl_xor_sync(~0u, s, o);
    if (!lane) out[(size_t)row*NVOC + w] = s;
}

// ---------------- host orchestration ----------------
extern "C" void kernel_launch(void* const* d_in, const int* in_sizes, int n_in,
                              void* d_out, int out_size) {
    const int*   value = (const int*)  d_in[0];
    const int*   depth = (const int*)  d_in[1];
    const int*   pos   = (const int*)  d_in[2];
    const float* sos   = (const float*)d_in[3];
    const float* tok   = (const float*)d_in[4];
    const float* dep   = (const float*)d_in[5];
    const float* pemb  = (const float*)d_in[6];
    const float* ln1s  = (const float*)d_in[7];
    const float* ln1b  = (const float*)d_in[8];
    const float* Wq    = (const float*)d_in[9];
    const float* Wk    = (const float*)d_in[10];
    const float* Wv    = (const float*)d_in[11];
    const float* Wo    = (const float*)d_in[12];
    const float* means = (const float*)d_in[13];
    const float* ln2s  = (const float*)d_in[14];
    const float* ln2b  = (const float*)d_in[15];
    const float* W1    = (const float*)d_in[16];
    const float* b1    = (const float*)d_in[17];
    const float* W2    = (const float*)d_in[18];
    const float* b2    = (const float*)d_in[19];
    const float* hw    = (const float*)d_in[20];
    float* out = (float*)d_out;

    float* base = nullptr;
    cudaGetSymbolAddress((void**)&base, g_buf);
    int* gidx = nullptr;
    cudaGetSymbolAddress((void**)&gidx, g_idx);
    __nv_bfloat16* wt = nullptr;
    cudaGetSymbolAddress((void**)&wt, g_wt);
    __nv_bfloat16* wt_lo = wt + WT_TOT;

    float* x     = base;
    __nv_bfloat16* h_hi = (__nv_bfloat16*)(base + 1*BSE);
    __nv_bfloat16* h_lo = h_hi + BSE;
    float* q     = base + 2*BSE;
    float* k     = base + 3*BSE;
    float* v     = base + 4*BSE;
    float* dists = base + 5*BSE;
    float* oacc  = base + 6*BSE;
    __nv_bfloat16* ab_hi = (__nv_bfloat16*)(base + 7*BSE);
    __nv_bfloat16* ab_lo = ab_hi + BSE;
    __nv_bfloat16* ff_hi = (__nv_bfloat16*)(base + 8*BSE);
    __nv_bfloat16* ff_lo = ff_hi + (size_t)BS*FF;
    float* qn    = base + 12*BSE;
    float* mn    = qn + BHS;
    float* cnt   = mn + 512;

    cudaFuncSetAttribute(attn_kernel, cudaFuncAttributeMaxDynamicSharedMemorySize, ATTN_SMEM_BYTES);
    cudaFuncSetAttribute(gemm_mma<0>, cudaFuncAttributeMaxDynamicSharedMemorySize, GT_SMEM);
    cudaFuncSetAttribute(gemm_mma<1>, cudaFuncAttributeMaxDynamicSharedMemorySize, GT_SMEM);
    cudaFuncSetAttribute(gemm_mma<2>, cudaFuncAttributeMaxDynamicSharedMemorySize, GT_SMEM);
    cudaFuncSetAttribute(gemm_mma<3>, cudaFuncAttributeMaxDynamicSharedMemorySize, GT_SMEM);

    wtrans_all<<<LL*3072, dim3(32,8)>>>(Wq, Wk, Wv, Wo, W1, W2, wt, wt_lo);
    embed_kernel<<<BS, 256>>>(value, depth, pos, sos, tok, dep, pemb, x);

    const int M = BS;
    dim3 gQKV(1536/128, M/128);    // fused QKV: N=1536
    dim3 g512(512/128, M/128);
    dim3 gFF(FF/128, M/128);

    for (int l = 0; l < LL; l++) {
        size_t lb = (size_t)l * WT_LAYER;
        const __nv_bfloat16* wqkv  = wt + lb;           // wq|wk|wv contiguous [1536, 512]
        const __nv_bfloat16* wqkvl = wt_lo + lb;
        const __nv_bfloat16* wot = wt + lb + 786432,  *wotl = wt_lo + lb + 786432;
        const __nv_bfloat16* w1t = wt + lb + 1048576, *w1tl = wt_lo + lb + 1048576;
        const __nv_bfloat16* w2t = wt + lb + 2097152, *w2tl = wt_lo + lb + 2097152;
        const float* ml = means + (size_t)l*HH*CC*DD;

        ln_kernel<<<BS, 256>>>(x, ln1s + l*EE, ln1b + l*EE, h_hi, h_lo);
        gemm_mma<0><<<gQKV, 256, GT_SMEM>>>(h_hi, h_lo, wqkv, wqkvl, nullptr, q, nullptr, nullptr, M, 1536, 512);

        rownorm_kernel<<<(BHS*32)/256, 256>>>(q, qn, BHS);
        rownorm_kernel<<<(HH*CC*32)/256, 256>>>(ml, mn, HH*CC);
        dists_kernel<<<dim3(SS/4, BB*HH), 256>>>(q, qn, ml, mn, dists);
        topk_kernel<<<BB*HH*CC, 256>>>(dists, gidx);

        cudaMemsetAsync(oacc, 0, BSE * sizeof(float));
        cudaMemsetAsync(cnt, 0, BHS * sizeof(float));
        attn_kernel<<<BB*HH*CC, 256, ATTN_SMEM_BYTES>>>(q, k, v, value, gidx, oacc, cnt);
        finalize_kernel<<<BS, 256>>>(oacc, cnt, ab_hi, ab_lo);
        gemm_mma<1><<<g512, 256, GT_SMEM>>>(ab_hi, ab_lo, wot, wotl, nullptr, x, nullptr, nullptr, M, 512, 512);

        ln_kernel<<<BS, 256>>>(x, ln2s + l*EE, ln2b + l*EE, h_hi, h_lo);
        gemm_mma<2><<<gFF, 256, GT_SMEM>>>(h_hi, h_lo, w1t, w1tl, b1 + l*FF, nullptr, ff_hi, ff_lo, M, FF, 512);
        gemm_mma<3><<<g512, 256, GT_SMEM>>>(ff_hi, ff_lo, w2t, w2tl, b2 + l*EE, x, nullptr, nullptr, M, 512, FF);
    }

    head_kernel<<<BS, NVOC*32>>>(x, hw, out);
}

// round 12
// speedup vs baseline: 1.7795x; 1.0263x over previous
#include <cuda_runtime.h>
#include <cuda_bf16.h>
#include <cstdint>
#include <math.h>

#define BB 4
#define SS 4096
#define EE 512
#define HH 8
#define DD 64
#define CC 64
#define WW 64
#define LL 4
#define FF 2048
#define NVOC 17

#define BS (BB*SS)                 // 16384 rows
#define BSE ((size_t)BS*EE)        // 8388608
#define BHS (BB*HH*SS)             // 131072

// ---------------- device scratch (no allocations allowed) ----------------
__device__ float g_buf[12*BSE + BHS + 512 + BHS];
__device__ int   g_idx[BB*HH*CC*WW];
#define WT_LAYER 3145728
#define WT_TOT   ((size_t)LL*WT_LAYER)
__device__ __nv_bfloat16 g_wt[2*WT_TOT];   // [hi | lo]

// ================= PTX helpers =================
__device__ __forceinline__ uint32_t smem_u32(const void* p) {
    uint32_t a;
    asm("{ .reg .u64 t; cvta.to.shared.u64 t, %1; cvt.u32.u64 %0, t; }" : "=r"(a) : "l"(p));
    return a;
}
__device__ __forceinline__ void cp16(uint32_t saddr, const void* gptr) {
    asm volatile("cp.async.cg.shared.global [%0], [%1], 16;" :: "r"(saddr), "l"(gptr));
}
__device__ __forceinline__ void cp_commit() { asm volatile("cp.async.commit_group;" ::: "memory"); }
template<int N> __device__ __forceinline__ void cp_wait() { asm volatile("cp.async.wait_group %0;" :: "n"(N) : "memory"); }

#define LDSM4(r0,r1,r2,r3,addr) \
    asm volatile("ldmatrix.sync.aligned.m8n8.x4.shared.b16 {%0,%1,%2,%3}, [%4];" \
        : "=r"(r0), "=r"(r1), "=r"(r2), "=r"(r3) : "r"(addr))

#define MMA16816(c, a, b0, b1) \
    asm volatile("mma.sync.aligned.m16n8k16.row.col.f32.bf16.bf16.f32 " \
        "{%0,%1,%2,%3}, {%4,%5,%6,%7}, {%8,%9}, {%0,%1,%2,%3};" \
        : "+f"((c)[0]), "+f"((c)[1]), "+f"((c)[2]), "+f"((c)[3]) \
        : "r"((a)[0]), "r"((a)[1]), "r"((a)[2]), "r"((a)[3]), "r"(b0), "r"(b1))

// ---------------- embedding + shift-right ----------------
__global__ void embed_kernel(const int* __restrict__ value, const int* __restrict__ depth,
                             const int* __restrict__ pos, const float* __restrict__ sos,
                             const float* __restrict__ tok, const float* __restrict__ dep,
                             const float* __restrict__ pemb, float* __restrict__ x) {
    int row = blockIdx.x;
    int b = row >> 12, s = row & 4095;
    float* xr = x + (size_t)row * EE;
    if (s == 0) {
        for (int i = threadIdx.x; i < EE; i += blockDim.x) xr[i] = sos[i];
        return;
    }
    int sp = s - 1;
    int v  = value[b*SS + sp];
    int dp = depth[b*SS + sp];
    int p0 = pos[(b*SS + sp)*3 + 0];
    int p1 = pos[(b*SS + sp)*3 + 1];
    int p2 = pos[(b*SS + sp)*3 + 2];
    const float* t0 = tok + (size_t)v*EE;
    const float* d0 = dep + (size_t)dp*EE;
    const float* e0 = pemb + ((size_t)0*65 + p0)*EE;
    const float* e1 = pemb + ((size_t)1*65 + p1)*EE;
    const float* e2 = pemb + ((size_t)2*65 + p2)*EE;
    for (int i = threadIdx.x; i < EE; i += blockDim.x)
        xr[i] = t0[i] + d0[i] + e0[i] + e1[i] + e2[i];
}

// ---------------- layernorm -> bf16 hi/lo ----------------
__global__ void ln_kernel(const float* __restrict__ x, const float* __restrict__ sc,
                          const float* __restrict__ bi, __nv_bfloat16* __restrict__ ohi,
                          __nv_bfloat16* __restrict__ olo) {
    int row = blockIdx.x;
    const float* xr = x + (size_t)row * EE;
    __shared__ float red[256];
    int tid = threadIdx.x;
    float v0 = xr[tid], v1 = xr[tid + 256];
    red[tid] = v0 + v1;
    __syncthreads();
    for (int st = 128; st > 0; st >>= 1) { if (tid < st) red[tid] += red[tid + st]; __syncthreads(); }
    float mean = red[0] * (1.f/512.f);
    __syncthreads();
    float d0 = v0 - mean, d1 = v1 - mean;
    red[tid] = d0*d0 + d1*d1;
    __syncthreads();
    for (int st = 128; st > 0; st >>= 1) { if (tid < st) red[tid] += red[tid + st]; __syncthreads(); }
    float var = red[0] * (1.f/512.f);
    float r = rsqrtf(var + 1e-5f);
    float y0 = d0 * r * sc[tid]       + bi[tid];
    float y1 = d1 * r * sc[tid + 256] + bi[tid + 256];
    __nv_bfloat16 h0 = __float2bfloat16(y0);
    __nv_bfloat16 h1 = __float2bfloat16(y1);
    size_t base = (size_t)row * EE;
    ohi[base + tid]       = h0;
    ohi[base + tid + 256] = h1;
    olo[base + tid]       = __float2bfloat16(y0 - __bfloat162float(h0));
    olo[base + tid + 256] = __float2bfloat16(y1 - __bfloat162float(h1));
}

// ---------------- ALL weights transpose + bf16 split in ONE launch ----------------
__global__ void wtrans_all(const float* __restrict__ Wq, const float* __restrict__ Wk,
                           const float* __restrict__ Wv, const float* __restrict__ Wo,
                           const float* __restrict__ W1, const float* __restrict__ W2,
                           __nv_bfloat16* __restrict__ hi_base, __nv_bfloat16* __restrict__ lo_base) {
    __shared__ float t[32][33];
    int bid = blockIdx.x;
    int l = bid / 3072, r = bid % 3072;
    const float* W; int K, N, tile; size_t off;
    if (r < 1024) {
        int ty = r >> 8; tile = r & 255; K = 512; N = 512;
        const float* Ws = (ty == 0) ? Wq : (ty == 1) ? Wk : (ty == 2) ? Wv : Wo;
        W = Ws + (size_t)l*512*512;
        off = (size_t)l*WT_LAYER + (size_t)ty*262144;
    } else if (r < 2048) {
        tile = r - 1024; K = 512; N = 2048;
        W = W1 + (size_t)l*512*2048;
        off = (size_t)l*WT_LAYER + 1048576;
    } else {
        tile = r - 2048; K = 2048; N = 512;
        W = W2 + (size_t)l*2048*512;
        off = (size_t)l*WT_LAYER + 2097152;
    }
    __nv_bfloat16* hi = hi_base + off;
    __nv_bfloat16* lo = lo_base + off;
    int tilesN = N >> 5;
    int n0 = (tile % tilesN) * 32, k0 = (tile / tilesN) * 32;
    for (int i = threadIdx.y; i < 32; i += 8)
        t[i][threadIdx.x] = W[(size_t)(k0 + i) * N + n0 + threadIdx.x];
    __syncthreads();
    for (int i = threadIdx.y; i < 32; i += 8) {
        int n = n0 + i, k = k0 + threadIdx.x;
        float v = t[threadIdx.x][i];
        __nv_bfloat16 h = __float2bfloat16(v);
        hi[(size_t)n*K + k] = h;
        lo[(size_t)n*K + k] = __float2bfloat16(v - __bfloat162float(h));
    }
}

// ---------------- HMMA GEMM: C[M,N] = A[M,K] @ B^T (B stored [N,K]) ----------------
// bf16x3: D = Ahi*Bhi + Alo*Bhi + Ahi*Blo, fp32 accumulate.
// K-chunk 32 (64B rows), 3-stage cp.async pipeline, pass-separated MMA.
// 96 KB smem + <=128 regs -> 2 CTAs/SM.
// MODE: 0 = fused-QKV splithead fp32 (N=1536, which=col>>9)   1 = resid fp32 (Wo)
//       2 = bias+gelu -> bf16 hi/lo (W1)   3 = bias+resid fp32 (W2)
#define STG_B 8192                  // per-array stage: 128 rows * 64 B
#define STAGE_B (4*STG_B)           // Ahi|Alo|Bhi|Blo = 32 KB
#define NSTAGES 3
#define GT_SMEM (NSTAGES*STAGE_B)   // 98304

__device__ __forceinline__ uint32_t swz64(int r, int u) {
    return (uint32_t)(r*64 + ((u ^ ((r >> 1) & 3)) << 4));
}

__device__ __forceinline__ float gelu_f(float x) {
    float x3 = x * x * x;
    return 0.5f * x * (1.0f + tanhf(0.7978845608028654f * (x + 0.044715f * x3)));
}

template<int MODE>
__global__ void __launch_bounds__(256, 2) gemm_mma(
    const __nv_bfloat16* __restrict__ Ahi, const __nv_bfloat16* __restrict__ Alo,
    const __nv_bfloat16* __restrict__ Bhi, const __nv_bfloat16* __restrict__ Blo,
    const float* __restrict__ bias, float* __restrict__ Cf,
    __nv_bfloat16* __restrict__ Chi, __nv_bfloat16* __restrict__ Clo,
    int M, int N, int K)
{
    extern __shared__ char sm[];
    uint32_t sb = smem_u32(sm);
    int tid = threadIdx.x, wid = tid >> 5, lane = tid & 31;
    int mrow = blockIdx.y * 128, ncol = blockIdx.x * 128;
    int wm = (wid >> 1) * 32;       // 4 m-warps
    int wn = (wid & 1) * 64;        // 2 n-warps

    // cp.async loader: thread -> (row, two 16B units) over 64B rows
    int lr = tid >> 1;
    int lu0 = (tid & 1) * 2;
    const __nv_bfloat16* gAh = Ahi + (size_t)(mrow + lr) * K;
    const __nv_bfloat16* gAl = Alo + (size_t)(mrow + lr) * K;
    const __nv_bfloat16* gBh = Bhi + (size_t)(ncol + lr) * K;
    const __nv_bfloat16* gBl = Blo + (size_t)(ncol + lr) * K;

    int nch = K >> 5;

    const int m_off = ((lane >> 3) & 1) * 8 + (lane & 7);
    const int a_ku  = (lane >> 4);
    const int n_off = ((lane >> 4) << 3) + (lane & 7);
    const int b_ku  = ((lane >> 3) & 1);

    float acc[2][8][4] = {};

    // prologue: fill NSTAGES-1 stages (chunks 0..NSTAGES-2)
    #pragma unroll
    for (int c = 0; c < NSTAGES-1; c++) {
        uint32_t bufb = sb + c * STAGE_B;
        int koff = c << 5;
        #pragma unroll
        for (int j = 0; j < 2; j++) {
            int u = lu0 + j;
            uint32_t so = swz64(lr, u);
            int ge = koff + u * 8;
            cp16(bufb + 0*STG_B + so, gAh + ge);
            cp16(bufb + 1*STG_B + so, gAl + ge);
            cp16(bufb + 2*STG_B + so, gBh + ge);
            cp16(bufb + 3*STG_B + so, gBl + ge);
        }
        cp_commit();
    }

    for (int c = 0; c < nch; c++) {
        int cn = c + NSTAGES-1;
        if (cn < nch) {
            uint32_t bufb = sb + (cn % NSTAGES) * STAGE_B;
            int koff = cn << 5;
            #pragma unroll
            for (int j = 0; j < 2; j++) {
                int u = lu0 + j;
                uint32_t so = swz64(lr, u);
                int ge = koff + u * 8;
                cp16(bufb + 0*STG_B + so, gAh + ge);
                cp16(bufb + 1*STG_B + so, gAl + ge);
                cp16(bufb + 2*STG_B + so, gBh + ge);
                cp16(bufb + 3*STG_B + so, gBl + ge);
            }
        }
        cp_commit();                 // always commit (empty groups keep accounting exact)
        cp_wait<NSTAGES-1>();        // chunk c's group is now complete
        __syncthreads();

        uint32_t base = sb + (c % NSTAGES) * STAGE_B;
        uint32_t aH = base, aL = base + STG_B, bH = base + 2*STG_B, bL = base + 3*STG_B;

        #pragma unroll
        for (int kk = 0; kk < 2; kk++) {
            uint32_t ah[2][4], al[2][4], bb[4][4];
            uint32_t offA[2], offB[4];
            #pragma unroll
            for (int t2 = 0; t2 < 2; t2++) {
                int r = wm + t2*16 + m_off;
                offA[t2] = swz64(r, kk*2 + a_ku);
                LDSM4(ah[t2][0], ah[t2][1], ah[t2][2], ah[t2][3], aH + offA[t2]);
                LDSM4(al[t2][0], al[t2][1], al[t2][2], al[t2][3], aL + offA[t2]);
            }
            #pragma unroll
            for (int p = 0; p < 4; p++) {
                int r = wn + p*16 + n_off;
                offB[p] = swz64(r, kk*2 + b_ku);
                LDSM4(bb[p][0], bb[p][1], bb[p][2], bb[p][3], bH + offB[p]);
            }
            // pass 1: Ahi*Bhi
            #pragma unroll
            for (int t2 = 0; t2 < 2; t2++)
                #pragma unroll
                for (int p = 0; p < 4; p++) {
                    MMA16816(acc[t2][2*p],   ah[t2], bb[p][0], bb[p][1]);
                    MMA16816(acc[t2][2*p+1], ah[t2], bb[p][2], bb[p][3]);
                }
            // pass 2: Alo*Bhi
            #pragma unroll
            for (int t2 = 0; t2 < 2; t2++)
                #pragma unroll
                for (int p = 0; p < 4; p++) {
                    MMA16816(acc[t2][2*p],   al[t2], bb[p][0], bb[p][1]);
                    MMA16816(acc[t2][2*p+1], al[t2], bb[p][2], bb[p][3]);
                }
            // pass 3: Ahi*Blo
            #pragma unroll
            for (int p = 0; p < 4; p++)
                LDSM4(bb[p][0], bb[p][1], bb[p][2], bb[p][3], bL + offB[p]);
            #pragma unroll
            for (int t2 = 0; t2 < 2; t2++)
                #pragma unroll
                for (int p = 0; p < 4; p++) {
                    MMA16816(acc[t2][2*p],   ah[t2], bb[p][0], bb[p][1]);
                    MMA16816(acc[t2][2*p+1], ah[t2], bb[p][2], bb[p][3]);
                }
        }
        __syncthreads();             // protect stage reuse (writers at iter c+1)
    }

    // ---------------- epilogue ----------------
    #pragma unroll
    for (int t2 = 0; t2 < 2; t2++) {
        int row0 = mrow + wm + t2*16 + (lane >> 2);
        #pragma unroll
        for (int p8 = 0; p8 < 8; p8++) {
            int col = ncol + wn + p8*8 + (lane & 3)*2;
            #pragma unroll
            for (int half = 0; half < 2; half++) {
                int row = row0 + half*8;
                float v0 = acc[t2][p8][half*2 + 0];
                float v1 = acc[t2][p8][half*2 + 1];
                if (MODE == 0) {
                    int which = col >> 9;         // 0=q,1=k,2=v
                    int c2 = col & 511;
                    int b = row >> 12, s = row & 4095;
                    int hh = c2 >> 6, dd = c2 & 63;
                    float* dst = Cf + (size_t)which*BSE;
                    *(float2*)&dst[(((size_t)b*HH + hh)*SS + s)*64 + dd] = make_float2(v0, v1);
                } else if (MODE == 1) {
                    float2* pp = (float2*)&Cf[(size_t)row*N + col];
                    float2 t = *pp; t.x += v0; t.y += v1; *pp = t;
                } else if (MODE == 2) {
                    float y0 = gelu_f(v0 + bias[col]);
                    float y1 = gelu_f(v1 + bias[col+1]);
                    __nv_bfloat16 h0 = __float2bfloat16(y0), h1 = __float2bfloat16(y1);
                    __nv_bfloat162 hh2; hh2.x = h0; hh2.y = h1;
                    __nv_bfloat162 ll2;
                    ll2.x = __float2bfloat16(y0 - __bfloat162float(h0));
                    ll2.y = __float2bfloat16(y1 - __bfloat162float(h1));
                    size_t o = (size_t)row*N + col;
                    *(__nv_bfloat162*)&Chi[o] = hh2;
                    *(__nv_bfloat162*)&Clo[o] = ll2;
                } else {
                    float2* pp = (float2*)&Cf[(size_t)row*N + col];
                    float2 t = *pp;
                    t.x += v0 + bias[col]; t.y += v1 + bias[col+1];
                    *pp = t;
                }
            }
        }
    }
}

// ---------------- row norms ----------------
__global__ void rownorm_kernel(const float* __restrict__ a, float* __restrict__ n, int rows) {
    int gw = (blockIdx.x * blockDim.x + threadIdx.x) >> 5;
    int lane = threadIdx.x & 31;
    if (gw >= rows) return;
    const float* r = a + (size_t)gw * 64;
    float v = r[lane]*r[lane] + r[lane+32]*r[lane+32];
    #pragma unroll
    for (int o = 16; o; o >>= 1) v += __shfl_xor_sync(~0u, v, o);
    if (!lane) n[gw] = sqrtf(v);
}

// ---------------- cosine dists: 64 s-rows per block (means loaded once) ----------------
__global__ void dists_kernel(const float* __restrict__ q, const float* __restrict__ qn,
                             const float* __restrict__ means_l, const float* __restrict__ mn,
                             float* __restrict__ dists) {
    __shared__ float msm[64*65];
    __shared__ float qs[4*65];
    int bh = blockIdx.y;
    int h  = bh & 7;
    int tid = threadIdx.x;
    for (int e = tid; e < 4096; e += 256) {
        int c = e >> 6, d = e & 63;
        msm[c*65 + d] = means_l[(size_t)h*CC*DD + c*64 + d];
    }
    int sbase = blockIdx.x * 64;
    for (int sc4 = 0; sc4 < 64; sc4 += 4) {
        __syncthreads();              // readers of prev qs done; msm ready on first iter
        {
            int si = tid >> 6, d = tid & 63;
            qs[si*65 + d] = q[((size_t)bh*SS + sbase + sc4 + si)*DD + d];
        }
        __syncthreads();
        int c = tid >> 2, si = tid & 3;
        int s = sbase + sc4 + si;
        float dot = 0.f;
        #pragma unroll
        for (int d = 0; d < 64; d++) dot += qs[si*65 + d] * msm[c*65 + d];
        float denom = (qn[(size_t)bh*SS + s] + 1e-8f) * (mn[h*CC + c] + 1e-8f);
        dists[((size_t)bh*CC + c)*SS + s] = dot / denom;
    }
}

// ---------------- top-64 per (b,h,c) ----------------
__global__ void topk_kernel(const float* __restrict__ dists, int* __restrict__ idx) {
    __shared__ float sv[SS];
    __shared__ float rv[256];
    __shared__ int   ri[256];
    int bid = blockIdx.x;
    int tid = threadIdx.x;
    const float* dr = dists + (size_t)bid * SS;
    for (int i = tid; i < SS; i += 256) sv[i] = dr[i];
    __syncthreads();
    for (int t = 0; t < WW; t++) {
        float bv = -INFINITY; int bi = SS;
        for (int i = tid; i < SS; i += 256) {
            float v = sv[i];
            if (v > bv || (v == bv && i < bi)) { bv = v; bi = i; }
        }
        rv[tid] = bv; ri[tid] = bi;
        __syncthreads();
        for (int st = 128; st > 0; st >>= 1) {
            if (tid < st) {
                if (rv[tid+st] > rv[tid] || (rv[tid+st] == rv[tid] && ri[tid+st] < ri[tid])) {
                    rv[tid] = rv[tid+st]; ri[tid] = ri[tid+st];
                }
            }
            __syncthreads();
        }
        if (tid == 0) { idx[bid*WW + t] = ri[0]; sv[ri[0]] = -INFINITY; }
        __syncthreads();
    }
}

// ---------------- bucketed attention + scatter-add ----------------
#define ATTN_SMEM_BYTES ((128 + 4*64*65) * 4)
__global__ void attn_kernel(const float* __restrict__ q, const float* __restrict__ k,
                            const float* __restrict__ v, const int* __restrict__ value,
                            const int* __restrict__ idx, float* __restrict__ oacc,
                            float* __restrict__ cnt) {
    extern __shared__ float smf[];
    int*   ids = (int*)smf;
    float* km  = smf + 64;
    float* qb  = smf + 128;
    float* kb  = qb + 64*65;
    float* vb  = kb + 64*65;
    float* sc  = vb + 64*65;
    int bid = blockIdx.x;
    int bh  = bid >> 6;
    int b   = bid >> 9;
    int tid = threadIdx.x;
    if (tid < 64) {
        int g = idx[bid*WW + tid];
        ids[tid] = g;
        km[tid] = (value[b*SS + g] != 0) ? 1.f : 0.f;
    }
    __syncthreads();
    for (int e = tid; e < 4096; e += 256) {
        int i = e >> 6, d = e & 63;
        size_t base = ((size_t)bh*SS + ids[i])*DD + d;
        qb[i*65 + d] = q[base];
        kb[i*65 + d] = k[base];
        vb[i*65 + d] = v[base];
    }
    __syncthreads();
    for (int e = tid; e < 4096; e += 256) {
        int i = e >> 6, j = e & 63;
        float s = 0.f;
        #pragma unroll
        for (int d = 0; d < 64; d++) s += qb[i*65 + d] * kb[j*65 + d];
        bool allowed = (ids[i] >= ids[j]) && (km[j] > 0.5f);
        sc[i*65 + j] = allowed ? s * 0.125f : -1e9f;
    }
    __syncthreads();
    {
        int w = tid >> 5, lane = tid & 31;
        for (int r = 0; r < 8; r++) {
            int i = w*8 + r;
            float v0 = sc[i*65 + lane], v1 = sc[i*65 + lane + 32];
            float m = fmaxf(v0, v1);
            #pragma unroll
            for (int o = 16; o; o >>= 1) m = fmaxf(m, __shfl_xor_sync(~0u, m, o));
            float e0 = expf(v0 - m), e1 = expf(v1 - m);
            float su = e0 + e1;
            #pragma unroll
            for (int o = 16; o; o >>= 1) su += __shfl_xor_sync(~0u, su, o);
            float inv = 1.f / su;
            sc[i*65 + lane]      = e0 * inv;
            sc[i*65 + lane + 32] = e1 * inv;
        }
    }
    __syncthreads();
    for (int e = tid; e < 4096; e += 256) {
        int i = e >> 6, d = e & 63;
        float s = 0.f;
        #pragma unroll
        for (int j = 0; j < 64; j++) s += sc[i*65 + j] * vb[j*65 + d];
        int g = ids[i];
        atomicAdd(&oacc[((size_t)bh*SS + g)*DD + d], s);
        if (d == 0) atomicAdd(&cnt[(size_t)bh*SS + g], 1.f);
    }
}

// ---------------- scatter-mean finalize -> bf16 hi/lo (B,S,E) ----------------
__global__ void finalize_kernel(const float* __restrict__ oacc, const float* __restrict__ cnt,
                                __nv_bfloat16* __restrict__ ahi, __nv_bfloat16* __restrict__ alo) {
    int row = blockIdx.x;
    int b = row >> 12, s = row & 4095;
    for (int e = threadIdx.x; e < EE; e += blockDim.x) {
        int hh = e >> 6, d = e & 63;
        int bh = b*HH + hh;
        float c = cnt[(size_t)bh*SS + s];
        float v = oacc[((size_t)bh*SS + s)*DD + d] / fmaxf(c, 1.f);
        __nv_bfloat16 h = __float2bfloat16(v);
        ahi[(size_t)row*EE + e] = h;
        alo[(size_t)row*EE + e] = __float2bfloat16(v - __bfloat162float(h));
    }
}

// ---------------- logit head ----------------
__global__ void head_kernel(const float* __restrict__ x, const float* __restrict__ hw,
                            float* __restrict__ out) {
    int row = blockIdx.x;
    int w = threadIdx.x >> 5, lane = threadIdx.x & 31;
    const float* xr = x + (size_t)row * EE;
    const float* wr = hw + (size_t)w * EE;
    float s = 0.f;
    for (int i = lane; i < EE; i += 32) s += xr[i] * wr[i];
    #pragma unroll
    for (int o = 16; o; o >>= 1) s += __shfl_xor_sync(~0u, s, o);
    if (!lane) out[(size_t)row*NVOC + w] = s;
}

// ---------------- host orchestration ----------------
extern "C" void kernel_launch(void* const* d_in, const int* in_sizes, int n_in,
                              void* d_out, int out_size) {
    const int*   value = (const int*)  d_in[0];
    const int*   depth = (const int*)  d_in[1];
    const int*   pos   = (const int*)  d_in[2];
    const float* sos   = (const float*)d_in[3];
    const float* tok   = (const float*)d_in[4];
    const float* dep   = (const float*)d_in[5];
    const float* pemb  = (const float*)d_in[6];
    const float* ln1s  = (const float*)d_in[7];
    const float* ln1b  = (const float*)d_in[8];
    const float* Wq    = (const float*)d_in[9];
    const float* Wk    = (const float*)d_in[10];
    const float* Wv    = (const float*)d_in[11];
    const float* Wo    = (const float*)d_in[12];
    const float* means = (const float*)d_in[13];
    const float* ln2s  = (const float*)d_in[14];
    const float* ln2b  = (const float*)d_in[15];
    const float* W1    = (const float*)d_in[16];
    const float* b1    = (const float*)d_in[17];
    const float* W2    = (const float*)d_in[18];
    const float* b2    = (const float*)d_in[19];
    const float* hw    = (const float*)d_in[20];
    float* out = (float*)d_out;

    float* base = nullptr;
    cudaGetSymbolAddress((void**)&base, g_buf);
    int* gidx = nullptr;
    cudaGetSymbolAddress((void**)&gidx, g_idx);
    __nv_bfloat16* wt = nullptr;
    cudaGetSymbolAddress((void**)&wt, g_wt);
    __nv_bfloat16* wt_lo = wt + WT_TOT;

    float* x     = base;
    __nv_bfloat16* h_hi = (__nv_bfloat16*)(base + 1*BSE);
    __nv_bfloat16* h_lo = h_hi + BSE;
    float* q     = base + 2*BSE;
    float* k     = base + 3*BSE;
    float* v     = base + 4*BSE;
    float* dists = base + 5*BSE;
    float* oacc  = base + 6*BSE;
    __nv_bfloat16* ab_hi = (__nv_bfloat16*)(base + 7*BSE);
    __nv_bfloat16* ab_lo = ab_hi + BSE;
    __nv_bfloat16* ff_hi = (__nv_bfloat16*)(base + 8*BSE);
    __nv_bfloat16* ff_lo = ff_hi + (size_t)BS*FF;
    float* qn    = base + 12*BSE;
    float* mn    = qn + BHS;
    float* cnt   = mn + 512;

    cudaFuncSetAttribute(attn_kernel, cudaFuncAttributeMaxDynamicSharedMemorySize, ATTN_SMEM_BYTES);
    cudaFuncSetAttribute(gemm_mma<0>, cudaFuncAttributeMaxDynamicSharedMemorySize, GT_SMEM);
    cudaFuncSetAttribute(gemm_mma<1>, cudaFuncAttributeMaxDynamicSharedMemorySize, GT_SMEM);
    cudaFuncSetAttribute(gemm_mma<2>, cudaFuncAttributeMaxDynamicSharedMemorySize, GT_SMEM);
    cudaFuncSetAttribute(gemm_mma<3>, cudaFuncAttributeMaxDynamicSharedMemorySize, GT_SMEM);

    wtrans_all<<<LL*3072, dim3(32,8)>>>(Wq, Wk, Wv, Wo, W1, W2, wt, wt_lo);
    embed_kernel<<<BS, 256>>>(value, depth, pos, sos, tok, dep, pemb, x);

    const int M = BS;
    dim3 gQKV(1536/128, M/128);    // fused QKV: N=1536
    dim3 g512(512/128, M/128);
    dim3 gFF(FF/128, M/128);

    for (int l = 0; l < LL; l++) {
        size_t lb = (size_t)l * WT_LAYER;
        const __nv_bfloat16* wqkv  = wt + lb;           // wq|wk|wv contiguous [1536, 512]
        const __nv_bfloat16* wqkvl = wt_lo + lb;
        const __nv_bfloat16* wot = wt + lb + 786432,  *wotl = wt_lo + lb + 786432;
        const __nv_bfloat16* w1t = wt + lb + 1048576, *w1tl = wt_lo + lb + 1048576;
        const __nv_bfloat16* w2t = wt + lb + 2097152, *w2tl = wt_lo + lb + 2097152;
        const float* ml = means + (size_t)l*HH*CC*DD;

        ln_kernel<<<BS, 256>>>(x, ln1s + l*EE, ln1b + l*EE, h_hi, h_lo);
        gemm_mma<0><<<gQKV, 256, GT_SMEM>>>(h_hi, h_lo, wqkv, wqkvl, nullptr, q, nullptr, nullptr, M, 1536, 512);

        rownorm_kernel<<<(BHS*32)/256, 256>>>(q, qn, BHS);
        rownorm_kernel<<<(HH*CC*32)/256, 256>>>(ml, mn, HH*CC);
        dists_kernel<<<dim3(SS/64, BB*HH), 256>>>(q, qn, ml, mn, dists);
        topk_kernel<<<BB*HH*CC, 256>>>(dists, gidx);

        cudaMemsetAsync(oacc, 0, BSE * sizeof(float));
        cudaMemsetAsync(cnt, 0, BHS * sizeof(float));
        attn_kernel<<<BB*HH*CC, 256, ATTN_SMEM_BYTES>>>(q, k, v, value, gidx, oacc, cnt);
        finalize_kernel<<<BS, 256>>>(oacc, cnt, ab_hi, ab_lo);
        gemm_mma<1><<<g512, 256, GT_SMEM>>>(ab_hi, ab_lo, wot, wotl, nullptr, x, nullptr, nullptr, M, 512, 512);

        ln_kernel<<<BS, 256>>>(x, ln2s + l*EE, ln2b + l*EE, h_hi, h_lo);
        gemm_mma<2><<<gFF, 256, GT_SMEM>>>(h_hi, h_lo, w1t, w1tl, b1 + l*FF, nullptr, ff_hi, ff_lo, M, FF, 512);
        gemm_mma<3><<<g512, 256, GT_SMEM>>>(ff_hi, ff_lo, w2t, w2tl, b2 + l*EE, x, nullptr, nullptr, M, 512, FF);
    }

    head_kernel<<<BS, NVOC*32>>>(x, hw, out);
}

// round 15
// speedup vs baseline: 2.0774x; 1.1675x over previous
#include <cuda_runtime.h>
#include <cuda_bf16.h>
#include <cstdint>
#include <math.h>

#define BB 4
#define SS 4096
#define EE 512
#define HH 8
#define DD 64
#define CC 64
#define WW 64
#define LL 4
#define FF 2048
#define NVOC 17

#define BS (BB*SS)                 // 16384 rows
#define BSE ((size_t)BS*EE)        // 8388608
#define BHS (BB*HH*SS)             // 131072

// ---------------- device scratch (no allocations allowed) ----------------
__device__ float g_buf[12*BSE + BHS + 512 + BHS];
__device__ int   g_idx[BB*HH*CC*WW];
#define WT_LAYER 3145728
#define WT_TOT   ((size_t)LL*WT_LAYER)
__device__ __nv_bfloat16 g_wt[2*WT_TOT];   // [hi | lo]

// ================= PTX helpers =================
__device__ __forceinline__ uint32_t smem_u32(const void* p) {
    uint32_t a;
    asm("{ .reg .u64 t; cvta.to.shared.u64 t, %1; cvt.u32.u64 %0, t; }" : "=r"(a) : "l"(p));
    return a;
}
__device__ __forceinline__ void cp16(uint32_t saddr, const void* gptr) {
    asm volatile("cp.async.cg.shared.global [%0], [%1], 16;" :: "r"(saddr), "l"(gptr));
}
__device__ __forceinline__ void cp_commit() { asm volatile("cp.async.commit_group;" ::: "memory"); }
template<int N> __device__ __forceinline__ void cp_wait() { asm volatile("cp.async.wait_group %0;" :: "n"(N) : "memory"); }

#define LDSM4(r0,r1,r2,r3,addr) \
    asm volatile("ldmatrix.sync.aligned.m8n8.x4.shared.b16 {%0,%1,%2,%3}, [%4];" \
        : "=r"(r0), "=r"(r1), "=r"(r2), "=r"(r3) : "r"(addr))

#define MMA16816(c, a, b0, b1) \
    asm volatile("mma.sync.aligned.m16n8k16.row.col.f32.bf16.bf16.f32 " \
        "{%0,%1,%2,%3}, {%4,%5,%6,%7}, {%8,%9}, {%0,%1,%2,%3};" \
        : "+f"((c)[0]), "+f"((c)[1]), "+f"((c)[2]), "+f"((c)[3]) \
        : "r"((a)[0]), "r"((a)[1]), "r"((a)[2]), "r"((a)[3]), "r"(b0), "r"(b1))

// ---------------- embedding + shift-right ----------------
__global__ void embed_kernel(const int* __restrict__ value, const int* __restrict__ depth,
                             const int* __restrict__ pos, const float* __restrict__ sos,
                             const float* __restrict__ tok, const float* __restrict__ dep,
                             const float* __restrict__ pemb, float* __restrict__ x) {
    int row = blockIdx.x;
    int b = row >> 12, s = row & 4095;
    float* xr = x + (size_t)row * EE;
    if (s == 0) {
        for (int i = threadIdx.x; i < EE; i += blockDim.x) xr[i] = sos[i];
        return;
    }
    int sp = s - 1;
    int v  = value[b*SS + sp];
    int dp = depth[b*SS + sp];
    int p0 = pos[(b*SS + sp)*3 + 0];
    int p1 = pos[(b*SS + sp)*3 + 1];
    int p2 = pos[(b*SS + sp)*3 + 2];
    const float* t0 = tok + (size_t)v*EE;
    const float* d0 = dep + (size_t)dp*EE;
    const float* e0 = pemb + ((size_t)0*65 + p0)*EE;
    const float* e1 = pemb + ((size_t)1*65 + p1)*EE;
    const float* e2 = pemb + ((size_t)2*65 + p2)*EE;
    for (int i = threadIdx.x; i < EE; i += blockDim.x)
        xr[i] = t0[i] + d0[i] + e0[i] + e1[i] + e2[i];
}

// ---------------- layernorm -> bf16 hi/lo ----------------
__global__ void ln_kernel(const float* __restrict__ x, const float* __restrict__ sc,
                          const float* __restrict__ bi, __nv_bfloat16* __restrict__ ohi,
                          __nv_bfloat16* __restrict__ olo) {
    int row = blockIdx.x;
    const float* xr = x + (size_t)row * EE;
    __shared__ float red[256];
    int tid = threadIdx.x;
    float v0 = xr[tid], v1 = xr[tid + 256];
    red[tid] = v0 + v1;
    __syncthreads();
    for (int st = 128; st > 0; st >>= 1) { if (tid < st) red[tid] += red[tid + st]; __syncthreads(); }
    float mean = red[0] * (1.f/512.f);
    __syncthreads();
    float d0 = v0 - mean, d1 = v1 - mean;
    red[tid] = d0*d0 + d1*d1;
    __syncthreads();
    for (int st = 128; st > 0; st >>= 1) { if (tid < st) red[tid] += red[tid + st]; __syncthreads(); }
    float var = red[0] * (1.f/512.f);
    float r = rsqrtf(var + 1e-5f);
    float y0 = d0 * r * sc[tid]       + bi[tid];
    float y1 = d1 * r * sc[tid + 256] + bi[tid + 256];
    __nv_bfloat16 h0 = __float2bfloat16(y0);
    __nv_bfloat16 h1 = __float2bfloat16(y1);
    size_t base = (size_t)row * EE;
    ohi[base + tid]       = h0;
    ohi[base + tid + 256] = h1;
    olo[base + tid]       = __float2bfloat16(y0 - __bfloat162float(h0));
    olo[base + tid + 256] = __float2bfloat16(y1 - __bfloat162float(h1));
}

// ---------------- ALL weights transpose + bf16 split in ONE launch ----------------
__global__ void wtrans_all(const float* __restrict__ Wq, const float* __restrict__ Wk,
                           const float* __restrict__ Wv, const float* __restrict__ Wo,
                           const float* __restrict__ W1, const float* __restrict__ W2,
                           __nv_bfloat16* __restrict__ hi_base, __nv_bfloat16* __restrict__ lo_base) {
    __shared__ float t[32][33];
    int bid = blockIdx.x;
    int l = bid / 3072, r = bid % 3072;
    const float* W; int K, N, tile; size_t off;
    if (r < 1024) {
        int ty = r >> 8; tile = r & 255; K = 512; N = 512;
        const float* Ws = (ty == 0) ? Wq : (ty == 1) ? Wk : (ty == 2) ? Wv : Wo;
        W = Ws + (size_t)l*512*512;
        off = (size_t)l*WT_LAYER + (size_t)ty*262144;
    } else if (r < 2048) {
        tile = r - 1024; K = 512; N = 2048;
        W = W1 + (size_t)l*512*2048;
        off = (size_t)l*WT_LAYER + 1048576;
    } else {
        tile = r - 2048; K = 2048; N = 512;
        W = W2 + (size_t)l*2048*512;
        off = (size_t)l*WT_LAYER + 2097152;
    }
    __nv_bfloat16* hi = hi_base + off;
    __nv_bfloat16* lo = lo_base + off;
    int tilesN = N >> 5;
    int n0 = (tile % tilesN) * 32, k0 = (tile / tilesN) * 32;
    for (int i = threadIdx.y; i < 32; i += 8)
        t[i][threadIdx.x] = W[(size_t)(k0 + i) * N + n0 + threadIdx.x];
    __syncthreads();
    for (int i = threadIdx.y; i < 32; i += 8) {
        int n = n0 + i, k = k0 + threadIdx.x;
        float v = t[threadIdx.x][i];
        __nv_bfloat16 h = __float2bfloat16(v);
        hi[(size_t)n*K + k] = h;
        lo[(size_t)n*K + k] = __float2bfloat16(v - __bfloat162float(h));
    }
}

// ---------------- HMMA GEMM: C[M,N] = A[M,K] @ B^T (B stored [N,K]) ----------------
// bf16x3: D = Ahi*Bhi + Alo*Bhi + Ahi*Blo, fp32 accumulate.
// K-chunk 32 (64B rows), 3-stage cp.async pipeline, ONE barrier per chunk.
// 96 KB smem + <=128 regs -> 2 CTAs/SM.
// MODE: 0 = fused-QKV splithead fp32 (N=1536, which=col>>9)   1 = resid fp32 (Wo)
//       2 = bias+gelu -> bf16 hi/lo (W1)   3 = bias+resid fp32 (W2)
#define STG_B 8192                  // per-array stage: 128 rows * 64 B
#define STAGE_B (4*STG_B)           // Ahi|Alo|Bhi|Blo = 32 KB
#define NSTAGES 3
#define GT_SMEM (NSTAGES*STAGE_B)   // 98304

__device__ __forceinline__ uint32_t swz64(int r, int u) {
    return (uint32_t)(r*64 + ((u ^ ((r >> 1) & 3)) << 4));
}

__device__ __forceinline__ float gelu_f(float x) {
    float x3 = x * x * x;
    return 0.5f * x * (1.0f + tanhf(0.7978845608028654f * (x + 0.044715f * x3)));
}

template<int MODE>
__global__ void __launch_bounds__(256, 2) gemm_mma(
    const __nv_bfloat16* __restrict__ Ahi, const __nv_bfloat16* __restrict__ Alo,
    const __nv_bfloat16* __restrict__ Bhi, const __nv_bfloat16* __restrict__ Blo,
    const float* __restrict__ bias, float* __restrict__ Cf,
    __nv_bfloat16* __restrict__ Chi, __nv_bfloat16* __restrict__ Clo,
    int M, int N, int K)
{
    extern __shared__ char sm[];
    uint32_t sb = smem_u32(sm);
    int tid = threadIdx.x, wid = tid >> 5, lane = tid & 31;
    int mrow = blockIdx.y * 128, ncol = blockIdx.x * 128;
    int wm = (wid >> 1) * 32;       // 4 m-warps
    int wn = (wid & 1) * 64;        // 2 n-warps

    // cp.async loader: thread -> (row, two 16B units) over 64B rows
    int lr = tid >> 1;
    int lu0 = (tid & 1) * 2;
    const __nv_bfloat16* gAh = Ahi + (size_t)(mrow + lr) * K;
    const __nv_bfloat16* gAl = Alo + (size_t)(mrow + lr) * K;
    const __nv_bfloat16* gBh = Bhi + (size_t)(ncol + lr) * K;
    const __nv_bfloat16* gBl = Blo + (size_t)(ncol + lr) * K;

    int nch = K >> 5;

    const int m_off = ((lane >> 3) & 1) * 8 + (lane & 7);
    const int a_ku  = (lane >> 4);
    const int n_off = ((lane >> 4) << 3) + (lane & 7);
    const int b_ku  = ((lane >> 3) & 1);

    float acc[2][8][4] = {};

    // prologue: fill NSTAGES-1 stages (chunks 0..NSTAGES-2)
    #pragma unroll
    for (int c = 0; c < NSTAGES-1; c++) {
        uint32_t bufb = sb + c * STAGE_B;
        int koff = c << 5;
        #pragma unroll
        for (int j = 0; j < 2; j++) {
            int u = lu0 + j;
            uint32_t so = swz64(lr, u);
            int ge = koff + u * 8;
            cp16(bufb + 0*STG_B + so, gAh + ge);
            cp16(bufb + 1*STG_B + so, gAl + ge);
            cp16(bufb + 2*STG_B + so, gBh + ge);
            cp16(bufb + 3*STG_B + so, gBl + ge);
        }
        cp_commit();
    }

    for (int c = 0; c < nch; c++) {
        cp_wait<NSTAGES-2>();        // chunk c's group complete
        __syncthreads();             // data visible to all; all warps done with stage (c-1)

        // prefetch chunk c+2 into stage (c+2)%3 == (c-1)%3 (safe: just synced)
        int cn = c + NSTAGES-1;
        if (cn < nch) {
            uint32_t bufb = sb + (cn % NSTAGES) * STAGE_B;
            int koff = cn << 5;
            #pragma unroll
            for (int j = 0; j < 2; j++) {
                int u = lu0 + j;
                uint32_t so = swz64(lr, u);
                int ge = koff + u * 8;
                cp16(bufb + 0*STG_B + so, gAh + ge);
                cp16(bufb + 1*STG_B + so, gAl + ge);
                cp16(bufb + 2*STG_B + so, gBh + ge);
                cp16(bufb + 3*STG_B + so, gBl + ge);
            }
        }
        cp_commit();                 // always one group per iteration (accounting exact)

        uint32_t base = sb + (c % NSTAGES) * STAGE_B;
        uint32_t aH = base, aL = base + STG_B, bH = base + 2*STG_B, bL = base + 3*STG_B;

        #pragma unroll
        for (int kk = 0; kk < 2; kk++) {
            uint32_t ah[2][4], al[2][4], bb[4][4];
            uint32_t offA[2], offB[4];
            #pragma unroll
            for (int t2 = 0; t2 < 2; t2++) {
                int r = wm + t2*16 + m_off;
                offA[t2] = swz64(r, kk*2 + a_ku);
                LDSM4(ah[t2][0], ah[t2][1], ah[t2][2], ah[t2][3], aH + offA[t2]);
                LDSM4(al[t2][0], al[t2][1], al[t2][2], al[t2][3], aL + offA[t2]);
            }
            #pragma unroll
            for (int p = 0; p < 4; p++) {
                int r = wn + p*16 + n_off;
                offB[p] = swz64(r, kk*2 + b_ku);
                LDSM4(bb[p][0], bb[p][1], bb[p][2], bb[p][3], bH + offB[p]);
            }
            // pass 1: Ahi*Bhi
            #pragma unroll
            for (int t2 = 0; t2 < 2; t2++)
                #pragma unroll
                for (int p = 0; p < 4; p++) {
                    MMA16816(acc[t2][2*p],   ah[t2], bb[p][0], bb[p][1]);
                    MMA16816(acc[t2][2*p+1], ah[t2], bb[p][2], bb[p][3]);
                }
            // pass 2: Alo*Bhi
            #pragma unroll
            for (int t2 = 0; t2 < 2; t2++)
                #pragma unroll
                for (int p = 0; p < 4; p++) {
                    MMA16816(acc[t2][2*p],   al[t2], bb[p][0], bb[p][1]);
                    MMA16816(acc[t2][2*p+1], al[t2], bb[p][2], bb[p][3]);
                }
            // pass 3: Ahi*Blo
            #pragma unroll
            for (int p = 0; p < 4; p++)
                LDSM4(bb[p][0], bb[p][1], bb[p][2], bb[p][3], bL + offB[p]);
            #pragma unroll
            for (int t2 = 0; t2 < 2; t2++)
                #pragma unroll
                for (int p = 0; p < 4; p++) {
                    MMA16816(acc[t2][2*p],   ah[t2], bb[p][0], bb[p][1]);
                    MMA16816(acc[t2][2*p+1], ah[t2], bb[p][2], bb[p][3]);
                }
        }
    }

    // ---------------- epilogue ----------------
    #pragma unroll
    for (int t2 = 0; t2 < 2; t2++) {
        int row0 = mrow + wm + t2*16 + (lane >> 2);
        #pragma unroll
        for (int p8 = 0; p8 < 8; p8++) {
            int col = ncol + wn + p8*8 + (lane & 3)*2;
            #pragma unroll
            for (int half = 0; half < 2; half++) {
                int row = row0 + half*8;
                float v0 = acc[t2][p8][half*2 + 0];
                float v1 = acc[t2][p8][half*2 + 1];
                if (MODE == 0) {
                    int which = col >> 9;         // 0=q,1=k,2=v
                    int c2 = col & 511;
                    int b = row >> 12, s = row & 4095;
                    int hh = c2 >> 6, dd = c2 & 63;
                    float* dst = Cf + (size_t)which*BSE;
                    *(float2*)&dst[(((size_t)b*HH + hh)*SS + s)*64 + dd] = make_float2(v0, v1);
                } else if (MODE == 1) {
                    float2* pp = (float2*)&Cf[(size_t)row*N + col];
                    float2 t = *pp; t.x += v0; t.y += v1; *pp = t;
                } else if (MODE == 2) {
                    float y0 = gelu_f(v0 + bias[col]);
                    float y1 = gelu_f(v1 + bias[col+1]);
                    __nv_bfloat16 h0 = __float2bfloat16(y0), h1 = __float2bfloat16(y1);
                    __nv_bfloat162 hh2; hh2.x = h0; hh2.y = h1;
                    __nv_bfloat162 ll2;
                    ll2.x = __float2bfloat16(y0 - __bfloat162float(h0));
                    ll2.y = __float2bfloat16(y1 - __bfloat162float(h1));
                    size_t o = (size_t)row*N + col;
                    *(__nv_bfloat162*)&Chi[o] = hh2;
                    *(__nv_bfloat162*)&Clo[o] = ll2;
                } else {
                    float2* pp = (float2*)&Cf[(size_t)row*N + col];
                    float2 t = *pp;
                    t.x += v0 + bias[col]; t.y += v1 + bias[col+1];
                    *pp = t;
                }
            }
        }
    }
}

// ---------------- row norms ----------------
__global__ void rownorm_kernel(const float* __restrict__ a, float* __restrict__ n, int rows) {
    int gw = (blockIdx.x * blockDim.x + threadIdx.x) >> 5;
    int lane = threadIdx.x & 31;
    if (gw >= rows) return;
    const float* r = a + (size_t)gw * 64;
    float v = r[lane]*r[lane] + r[lane+32]*r[lane+32];
    #pragma unroll
    for (int o = 16; o; o >>= 1) v += __shfl_xor_sync(~0u, v, o);
    if (!lane) n[gw] = sqrtf(v);
}

// ---------------- cosine dists: 64 s-rows per block (means loaded once) ----------------
__global__ void dists_kernel(const float* __restrict__ q, const float* __restrict__ qn,
                             const float* __restrict__ means_l, const float* __restrict__ mn,
                             float* __restrict__ dists) {
    __shared__ float msm[64*65];
    __shared__ float qs[4*65];
    int bh = blockIdx.y;
    int h  = bh & 7;
    int tid = threadIdx.x;
    for (int e = tid; e < 4096; e += 256) {
        int c = e >> 6, d = e & 63;
        msm[c*65 + d] = means_l[(size_t)h*CC*DD + c*64 + d];
    }
    int sbase = blockIdx.x * 64;
    for (int sc4 = 0; sc4 < 64; sc4 += 4) {
        __syncthreads();
        {
            int si = tid >> 6, d = tid & 63;
            qs[si*65 + d] = q[((size_t)bh*SS + sbase + sc4 + si)*DD + d];
        }
        __syncthreads();
        int c = tid >> 2, si = tid & 3;
        int s = sbase + sc4 + si;
        float dot = 0.f;
        #pragma unroll
        for (int d = 0; d < 64; d++) dot += qs[si*65 + d] * msm[c*65 + d];
        float denom = (qn[(size_t)bh*SS + s] + 1e-8f) * (mn[h*CC + c] + 1e-8f);
        dists[((size_t)bh*CC + c)*SS + s] = dot / denom;
    }
}

// ---------------- top-64 per (b,h,c): RADIX SELECT ----------------
// Selected SET is all the downstream math needs (outputs scatter by id; causal
// mask compares gathered ids) — order within the 64 slots is irrelevant.
// Tie-break matches jax: all keys > T, plus lowest-index keys == T.
__global__ void topk_kernel(const float* __restrict__ dists, int* __restrict__ idx) {
    __shared__ uint32_t keys[SS];        // 16 KB
    __shared__ int hist[256];
    __shared__ int ps[256];
    __shared__ int s_misc[4];            // 0: prefix, 1: k_remaining, 2: cnt_gt, 3: ebase
    int bid = blockIdx.x;
    int tid = threadIdx.x;
    const float* dr = dists + (size_t)bid * SS;

    // load + monotonic float->uint transform (ascending order preserved)
    for (int i = tid; i < SS; i += 256) {
        uint32_t b = __float_as_uint(dr[i]);
        keys[i] = (b & 0x80000000u) ? ~b : (b | 0x80000000u);
    }
    if (tid == 0) { s_misc[0] = 0; s_misc[1] = WW; s_misc[2] = 0; s_misc[3] = 0; }
    __syncthreads();

    // 4 radix rounds, MSB -> LSB, descending select of 64th largest
    #pragma unroll
    for (int bp = 3; bp >= 0; bp--) {
        int shift = bp * 8;
        uint32_t himask = (bp == 3) ? 0u : (0xFFFFFFFFu << (shift + 8));
        uint32_t prefix = (uint32_t)s_misc[0];
        hist[tid] = 0;
        __syncthreads();
        for (int i = tid; i < SS; i += 256) {
            uint32_t kk = keys[i];
            if ((kk & himask) == prefix)
                atomicAdd(&hist[(kk >> shift) & 255], 1);
        }
        __syncthreads();
        if (tid == 0) {
            int k = s_misc[1];
            int acc = 0;
            int d = 255;
            for (; d >= 0; d--) {
                acc += hist[d];
                if (acc >= k) break;
            }
            s_misc[1] = k - (acc - hist[d]);            // how many to take at digit d
            s_misc[0] = (int)(prefix | ((uint32_t)d << shift));
        }
        __syncthreads();
    }
    uint32_t T = (uint32_t)s_misc[0];

    // collect all keys > T (order-free, atomic slots)
    for (int i = tid; i < SS; i += 256) {
        if (keys[i] > T) {
            int p = atomicAdd(&s_misc[2], 1);
            idx[bid*WW + p] = i;
        }
    }
    __syncthreads();
    int G = s_misc[2];
    int kneed = WW - G;                                  // >=1 by construction

    // collect ==T in ascending index order (lowest-index tie-break, like jax)
    for (int chunk = 0; chunk < SS; chunk += 256) {
        int i = chunk + tid;
        int pred = (keys[i] == T) ? 1 : 0;
        ps[tid] = pred;
        __syncthreads();
        #pragma unroll
        for (int off = 1; off < 256; off <<= 1) {
            int v = (tid >= off) ? ps[tid - off] : 0;
            __syncthreads();
            ps[tid] += v;
            __syncthreads();
        }
        int excl = ps[tid] - pred;
        int ebase = s_misc[3];
        if (pred && (ebase + excl) < kneed)
            idx[bid*WW + G + ebase + excl] = i;
        __syncthreads();
        if (tid == 0) s_misc[3] = ebase + ps[255];
        __syncthreads();
        if (s_misc[3] >= kneed) break;
    }
}

// ---------------- bucketed attention + scatter-add ----------------
#define ATTN_SMEM_BYTES ((128 + 4*64*65) * 4)
__global__ void attn_kernel(const float* __restrict__ q, const float* __restrict__ k,
                            const float* __restrict__ v, const int* __restrict__ value,
                            const int* __restrict__ idx, float* __restrict__ oacc,
                            float* __restrict__ cnt) {
    extern __shared__ float smf[];
    int*   ids = (int*)smf;
    float* km  = smf + 64;
    float* qb  = smf + 128;
    float* kb  = qb + 64*65;
    float* vb  = kb + 64*65;
    float* sc  = vb + 64*65;
    int bid = blockIdx.x;
    int bh  = bid >> 6;
    int b   = bid >> 9;
    int tid = threadIdx.x;
    if (tid < 64) {
        int g = idx[bid*WW + tid];
        ids[tid] = g;
        km[tid] = (value[b*SS + g] != 0) ? 1.f : 0.f;
    }
    __syncthreads();
    for (int e = tid; e < 4096; e += 256) {
        int i = e >> 6, d = e & 63;
        size_t base = ((size_t)bh*SS + ids[i])*DD + d;
        qb[i*65 + d] = q[base];
        kb[i*65 + d] = k[base];
        vb[i*65 + d] = v[base];
    }
    __syncthreads();
    for (int e = tid; e < 4096; e += 256) {
        int i = e >> 6, j = e & 63;
        float s = 0.f;
        #pragma unroll
        for (int d = 0; d < 64; d++) s += qb[i*65 + d] * kb[j*65 + d];
        bool allowed = (ids[i] >= ids[j]) && (km[j] > 0.5f);
        sc[i*65 + j] = allowed ? s * 0.125f : -1e9f;
    }
    __syncthreads();
    {
        int w = tid >> 5, lane = tid & 31;
        for (int r = 0; r < 8; r++) {
            int i = w*8 + r;
            float v0 = sc[i*65 + lane], v1 = sc[i*65 + lane + 32];
            float m = fmaxf(v0, v1);
            #pragma unroll
            for (int o = 16; o; o >>= 1) m = fmaxf(m, __shfl_xor_sync(~0u, m, o));
            float e0 = expf(v0 - m), e1 = expf(v1 - m);
            float su = e0 + e1;
            #pragma unroll
            for (int o = 16; o; o >>= 1) su += __shfl_xor_sync(~0u, su, o);
            float inv = 1.f / su;
            sc[i*65 + lane]      = e0 * inv;
            sc[i*65 + lane + 32] = e1 * inv;
        }
    }
    __syncthreads();
    for (int e = tid; e < 4096; e += 256) {
        int i = e >> 6, d = e & 63;
        float s = 0.f;
        #pragma unroll
        for (int j = 0; j < 64; j++) s += sc[i*65 + j] * vb[j*65 + d];
        int g = ids[i];
        atomicAdd(&oacc[((size_t)bh*SS + g)*DD + d], s);
        if (d == 0) atomicAdd(&cnt[(size_t)bh*SS + g], 1.f);
    }
}

// ---------------- scatter-mean finalize -> bf16 hi/lo (B,S,E) ----------------
__global__ void finalize_kernel(const float* __restrict__ oacc, const float* __restrict__ cnt,
                                __nv_bfloat16* __restrict__ ahi, __nv_bfloat16* __restrict__ alo) {
    int row = blockIdx.x;
    int b = row >> 12, s = row & 4095;
    for (int e = threadIdx.x; e < EE; e += blockDim.x) {
        int hh = e >> 6, d = e & 63;
        int bh = b*HH + hh;
        float c = cnt[(size_t)bh*SS + s];
        float v = oacc[((size_t)bh*SS + s)*DD + d] / fmaxf(c, 1.f);
        __nv_bfloat16 h = __float2bfloat16(v);
        ahi[(size_t)row*EE + e] = h;
        alo[(size_t)row*EE + e] = __float2bfloat16(v - __bfloat162float(h));
    }
}

// ---------------- logit head ----------------
__global__ void head_kernel(const float* __restrict__ x, const float* __restrict__ hw,
                            float* __restrict__ out) {
    int row = blockIdx.x;
    int w = threadIdx.x >> 5, lane = threadIdx.x & 31;
    const float* xr = x + (size_t)row * EE;
    const float* wr = hw + (size_t)w * EE;
    float s = 0.f;
    for (int i = lane; i < EE; i += 32) s += xr[i] * wr[i];
    #pragma unroll
    for (int o = 16; o; o >>= 1) s += __shfl_xor_sync(~0u, s, o);
    if (!lane) out[(size_t)row*NVOC + w] = s;
}

// ---------------- host orchestration ----------------
extern "C" void kernel_launch(void* const* d_in, const int* in_sizes, int n_in,
                              void* d_out, int out_size) {
    const int*   value = (const int*)  d_in[0];
    const int*   depth = (const int*)  d_in[1];
    const int*   pos   = (const int*)  d_in[2];
    const float* sos   = (const float*)d_in[3];
    const float* tok   = (const float*)d_in[4];
    const float* dep   = (const float*)d_in[5];
    const float* pemb  = (const float*)d_in[6];
    const float* ln1s  = (const float*)d_in[7];
    const float* ln1b  = (const float*)d_in[8];
    const float* Wq    = (const float*)d_in[9];
    const float* Wk    = (const float*)d_in[10];
    const float* Wv    = (const float*)d_in[11];
    const float* Wo    = (const float*)d_in[12];
    const float* means = (const float*)d_in[13];
    const float* ln2s  = (const float*)d_in[14];
    const float* ln2b  = (const float*)d_in[15];
    const float* W1    = (const float*)d_in[16];
    const float* b1    = (const float*)d_in[17];
    const float* W2    = (const float*)d_in[18];
    const float* b2    = (const float*)d_in[19];
    const float* hw    = (const float*)d_in[20];
    float* out = (float*)d_out;

    float* base = nullptr;
    cudaGetSymbolAddress((void**)&base, g_buf);
    int* gidx = nullptr;
    cudaGetSymbolAddress((void**)&gidx, g_idx);
    __nv_bfloat16* wt = nullptr;
    cudaGetSymbolAddress((void**)&wt, g_wt);
    __nv_bfloat16* wt_lo = wt + WT_TOT;

    float* x     = base;
    __nv_bfloat16* h_hi = (__nv_bfloat16*)(base + 1*BSE);
    __nv_bfloat16* h_lo = h_hi + BSE;
    float* q     = base + 2*BSE;
    float* k     = base + 3*BSE;
    float* v     = base + 4*BSE;
    float* dists = base + 5*BSE;
    float* oacc  = base + 6*BSE;
    __nv_bfloat16* ab_hi = (__nv_bfloat16*)(base + 7*BSE);
    __nv_bfloat16* ab_lo = ab_hi + BSE;
    __nv_bfloat16* ff_hi = (__nv_bfloat16*)(base + 8*BSE);
    __nv_bfloat16* ff_lo = ff_hi + (size_t)BS*FF;
    float* qn    = base + 12*BSE;
    float* mn    = qn + BHS;
    float* cnt   = mn + 512;

    cudaFuncSetAttribute(attn_kernel, cudaFuncAttributeMaxDynamicSharedMemorySize, ATTN_SMEM_BYTES);
    cudaFuncSetAttribute(gemm_mma<0>, cudaFuncAttributeMaxDynamicSharedMemorySize, GT_SMEM);
    cudaFuncSetAttribute(gemm_mma<1>, cudaFuncAttributeMaxDynamicSharedMemorySize, GT_SMEM);
    cudaFuncSetAttribute(gemm_mma<2>, cudaFuncAttributeMaxDynamicSharedMemorySize, GT_SMEM);
    cudaFuncSetAttribute(gemm_mma<3>, cudaFuncAttributeMaxDynamicSharedMemorySize, GT_SMEM);

    wtrans_all<<<LL*3072, dim3(32,8)>>>(Wq, Wk, Wv, Wo, W1, W2, wt, wt_lo);
    embed_kernel<<<BS, 256>>>(value, depth, pos, sos, tok, dep, pemb, x);

    const int M = BS;
    dim3 gQKV(1536/128, M/128);    // fused QKV: N=1536
    dim3 g512(512/128, M/128);
    dim3 gFF(FF/128, M/128);

    for (int l = 0; l < LL; l++) {
        size_t lb = (size_t)l * WT_LAYER;
        const __nv_bfloat16* wqkv  = wt + lb;           // wq|wk|wv contiguous [1536, 512]
        const __nv_bfloat16* wqkvl = wt_lo + lb;
        const __nv_bfloat16* wot = wt + lb + 786432,  *wotl = wt_lo + lb + 786432;
        const __nv_bfloat16* w1t = wt + lb + 1048576, *w1tl = wt_lo + lb + 1048576;
        const __nv_bfloat16* w2t = wt + lb + 2097152, *w2tl = wt_lo + lb + 2097152;
        const float* ml = means + (size_t)l*HH*CC*DD;

        ln_kernel<<<BS, 256>>>(x, ln1s + l*EE, ln1b + l*EE, h_hi, h_lo);
        gemm_mma<0><<<gQKV, 256, GT_SMEM>>>(h_hi, h_lo, wqkv, wqkvl, nullptr, q, nullptr, nullptr, M, 1536, 512);

        rownorm_kernel<<<(BHS*32)/256, 256>>>(q, qn, BHS);
        rownorm_kernel<<<(HH*CC*32)/256, 256>>>(ml, mn, HH*CC);
        dists_kernel<<<dim3(SS/64, BB*HH), 256>>>(q, qn, ml, mn, dists);
        topk_kernel<<<BB*HH*CC, 256>>>(dists, gidx);

        cudaMemsetAsync(oacc, 0, BSE * sizeof(float));
        cudaMemsetAsync(cnt, 0, BHS * sizeof(float));
        attn_kernel<<<BB*HH*CC, 256, ATTN_SMEM_BYTES>>>(q, k, v, value, gidx, oacc, cnt);
        finalize_kernel<<<BS, 256>>>(oacc, cnt, ab_hi, ab_lo);
        gemm_mma<1><<<g512, 256, GT_SMEM>>>(ab_hi, ab_lo, wot, wotl, nullptr, x, nullptr, nullptr, M, 512, 512);

        ln_kernel<<<BS, 256>>>(x, ln2s + l*EE, ln2b + l*EE, h_hi, h_lo);
        gemm_mma<2><<<gFF, 256, GT_SMEM>>>(h_hi, h_lo, w1t, w1tl, b1 + l*FF, nullptr, ff_hi, ff_lo, M, FF, 512);
        gemm_mma<3><<<g512, 256, GT_SMEM>>>(ff_hi, ff_lo, w2t, w2tl, b2 + l*EE, x, nullptr, nullptr, M, 512, FF);
    }

    head_kernel<<<BS, NVOC*32>>>(x, hw, out);
}

// round 17
// speedup vs baseline: 2.3692x; 1.1404x over previous
#include <cuda_runtime.h>
#include <cuda_bf16.h>
#include <cuda_fp16.h>
#include <cstdint>
#include <math.h>

#define BB 4
#define SS 4096
#define EE 512
#define HH 8
#define DD 64
#define CC 64
#define WW 64
#define LL 4
#define FF 2048
#define NVOC 17

#define BS (BB*SS)                 // 16384 rows
#define BSE ((size_t)BS*EE)        // 8388608
#define BHS (BB*HH*SS)             // 131072

// ---------------- device scratch (no allocations allowed) ----------------
__device__ float g_buf[12*BSE + BHS + 512 + BHS];
__device__ int   g_idx[BB*HH*CC*WW];
#define WT_LAYER 3145728
#define WT_TOT   ((size_t)LL*WT_LAYER)
__device__ __nv_bfloat16 g_wt[2*WT_TOT];   // [hi | lo]; fp16 weights live in hi region

// ================= PTX helpers =================
__device__ __forceinline__ uint32_t smem_u32(const void* p) {
    uint32_t a;
    asm("{ .reg .u64 t; cvta.to.shared.u64 t, %1; cvt.u32.u64 %0, t; }" : "=r"(a) : "l"(p));
    return a;
}
__device__ __forceinline__ void cp16(uint32_t saddr, const void* gptr) {
    asm volatile("cp.async.cg.shared.global [%0], [%1], 16;" :: "r"(saddr), "l"(gptr));
}
__device__ __forceinline__ void cp_commit() { asm volatile("cp.async.commit_group;" ::: "memory"); }
template<int N> __device__ __forceinline__ void cp_wait() { asm volatile("cp.async.wait_group %0;" :: "n"(N) : "memory"); }

#define LDSM4(r0,r1,r2,r3,addr) \
    asm volatile("ldmatrix.sync.aligned.m8n8.x4.shared.b16 {%0,%1,%2,%3}, [%4];" \
        : "=r"(r0), "=r"(r1), "=r"(r2), "=r"(r3) : "r"(addr))

#define MMA16816(c, a, b0, b1) \
    asm volatile("mma.sync.aligned.m16n8k16.row.col.f32.bf16.bf16.f32 " \
        "{%0,%1,%2,%3}, {%4,%5,%6,%7}, {%8,%9}, {%0,%1,%2,%3};" \
        : "+f"((c)[0]), "+f"((c)[1]), "+f"((c)[2]), "+f"((c)[3]) \
        : "r"((a)[0]), "r"((a)[1]), "r"((a)[2]), "r"((a)[3]), "r"(b0), "r"(b1))

#define MMA16816H(c, a, b0, b1) \
    asm volatile("mma.sync.aligned.m16n8k16.row.col.f32.f16.f16.f32 " \
        "{%0,%1,%2,%3}, {%4,%5,%6,%7}, {%8,%9}, {%0,%1,%2,%3};" \
        : "+f"((c)[0]), "+f"((c)[1]), "+f"((c)[2]), "+f"((c)[3]) \
        : "r"((a)[0]), "r"((a)[1]), "r"((a)[2]), "r"((a)[3]), "r"(b0), "r"(b1))

// ---------------- embedding + shift-right ----------------
__global__ void embed_kernel(const int* __restrict__ value, const int* __restrict__ depth,
                             const int* __restrict__ pos, const float* __restrict__ sos,
                             const float* __restrict__ tok, const float* __restrict__ dep,
                             const float* __restrict__ pemb, float* __restrict__ x) {
    int row = blockIdx.x;
    int b = row >> 12, s = row & 4095;
    float* xr = x + (size_t)row * EE;
    if (s == 0) {
        for (int i = threadIdx.x; i < EE; i += blockDim.x) xr[i] = sos[i];
        return;
    }
    int sp = s - 1;
    int v  = value[b*SS + sp];
    int dp = depth[b*SS + sp];
    int p0 = pos[(b*SS + sp)*3 + 0];
    int p1 = pos[(b*SS + sp)*3 + 1];
    int p2 = pos[(b*SS + sp)*3 + 2];
    const float* t0 = tok + (size_t)v*EE;
    const float* d0 = dep + (size_t)dp*EE;
    const float* e0 = pemb + ((size_t)0*65 + p0)*EE;
    const float* e1 = pemb + ((size_t)1*65 + p1)*EE;
    const float* e2 = pemb + ((size_t)2*65 + p2)*EE;
    for (int i = threadIdx.x; i < EE; i += blockDim.x)
        xr[i] = t0[i] + d0[i] + e0[i] + e1[i] + e2[i];
}

// ---------------- layernorm -> 16-bit hi/lo (bf16 if f16==0, fp16 if f16==1) ----------------
__global__ void ln_kernel(const float* __restrict__ x, const float* __restrict__ sc,
                          const float* __restrict__ bi, __nv_bfloat16* __restrict__ ohi,
                          __nv_bfloat16* __restrict__ olo, int f16) {
    int row = blockIdx.x;
    const float* xr = x + (size_t)row * EE;
    __shared__ float red[256];
    int tid = threadIdx.x;
    float v0 = xr[tid], v1 = xr[tid + 256];
    red[tid] = v0 + v1;
    __syncthreads();
    for (int st = 128; st > 0; st >>= 1) { if (tid < st) red[tid] += red[tid + st]; __syncthreads(); }
    float mean = red[0] * (1.f/512.f);
    __syncthreads();
    float d0 = v0 - mean, d1 = v1 - mean;
    red[tid] = d0*d0 + d1*d1;
    __syncthreads();
    for (int st = 128; st > 0; st >>= 1) { if (tid < st) red[tid] += red[tid + st]; __syncthreads(); }
    float var = red[0] * (1.f/512.f);
    float r = rsqrtf(var + 1e-5f);
    float y0 = d0 * r * sc[tid]       + bi[tid];
    float y1 = d1 * r * sc[tid + 256] + bi[tid + 256];
    size_t base = (size_t)row * EE;
    if (f16) {
        __half h0 = __float2half_rn(y0), h1 = __float2half_rn(y1);
        ((__half*)ohi)[base + tid]       = h0;
        ((__half*)ohi)[base + tid + 256] = h1;
        ((__half*)olo)[base + tid]       = __float2half_rn(y0 - __half2float(h0));
        ((__half*)olo)[base + tid + 256] = __float2half_rn(y1 - __half2float(h1));
    } else {
        __nv_bfloat16 h0 = __float2bfloat16(y0);
        __nv_bfloat16 h1 = __float2bfloat16(y1);
        ohi[base + tid]       = h0;
        ohi[base + tid + 256] = h1;
        olo[base + tid]       = __float2bfloat16(y0 - __bfloat162float(h0));
        olo[base + tid + 256] = __float2bfloat16(y1 - __bfloat162float(h1));
    }
}

// ---------------- ALL weights transpose in ONE launch ----------------
// Wq/Wk/Wv -> bf16 hi/lo (routing-critical). Wo/W1/W2 -> fp16 single (into hi).
__global__ void wtrans_all(const float* __restrict__ Wq, const float* __restrict__ Wk,
                           const float* __restrict__ Wv, const float* __restrict__ Wo,
                           const float* __restrict__ W1, const float* __restrict__ W2,
                           __nv_bfloat16* __restrict__ hi_base, __nv_bfloat16* __restrict__ lo_base) {
    __shared__ float t[32][33];
    int bid = blockIdx.x;
    int l = bid / 3072, r = bid % 3072;
    const float* W; int K, N, tile; size_t off; bool f16s;
    if (r < 1024) {
        int ty = r >> 8; tile = r & 255; K = 512; N = 512;
        const float* Ws = (ty == 0) ? Wq : (ty == 1) ? Wk : (ty == 2) ? Wv : Wo;
        W = Ws + (size_t)l*512*512;
        off = (size_t)l*WT_LAYER + (size_t)ty*262144;
        f16s = (ty == 3);
    } else if (r < 2048) {
        tile = r - 1024; K = 512; N = 2048;
        W = W1 + (size_t)l*512*2048;
        off = (size_t)l*WT_LAYER + 1048576;
        f16s = true;
    } else {
        tile = r - 2048; K = 2048; N = 512;
        W = W2 + (size_t)l*2048*512;
        off = (size_t)l*WT_LAYER + 2097152;
        f16s = true;
    }
    __nv_bfloat16* hi = hi_base + off;
    __nv_bfloat16* lo = lo_base + off;
    int tilesN = N >> 5;
    int n0 = (tile % tilesN) * 32, k0 = (tile / tilesN) * 32;
    for (int i = threadIdx.y; i < 32; i += 8)
        t[i][threadIdx.x] = W[(size_t)(k0 + i) * N + n0 + threadIdx.x];
    __syncthreads();
    for (int i = threadIdx.y; i < 32; i += 8) {
        int n = n0 + i, k = k0 + threadIdx.x;
        float v = t[threadIdx.x][i];
        if (f16s) {
            ((__half*)hi)[(size_t)n*K + k] = __float2half_rn(v);
        } else {
            __nv_bfloat16 h = __float2bfloat16(v);
            hi[(size_t)n*K + k] = h;
            lo[(size_t)n*K + k] = __float2bfloat16(v - __bfloat162float(h));
        }
    }
}

// ---------------- HMMA GEMM: C[M,N] = A[M,K] @ B^T (B stored [N,K]) ----------------
// PREC 0: bf16x3 (Ahi*Bhi + Alo*Bhi + Ahi*Blo), 4 smem arrays/stage.
// PREC 1: fp16x2 (Ahi*Bh + Alo*Bh; weights single fp16), 3 smem arrays/stage.
// K-chunk 32 (64B rows), 3-stage cp.async, one barrier per chunk, 2 CTAs/SM.
// MODE: 0 = fused-QKV splithead fp32   1 = resid fp32 (Wo)
//       2 = bias+gelu -> fp16 hi/lo (W1)   3 = bias+resid fp32 (W2)
#define STG_B 8192                  // per-array stage: 128 rows * 64 B
#define NSTAGES 3
#define GT_SMEM0 (NSTAGES*4*STG_B)  // 98304 (bf16x3)
#define GT_SMEM1 (NSTAGES*3*STG_B)  // 73728 (fp16x2)

__device__ __forceinline__ uint32_t swz64(int r, int u) {
    return (uint32_t)(r*64 + ((u ^ ((r >> 1) & 3)) << 4));
}

__device__ __forceinline__ float gelu_f(float x) {
    float x3 = x * x * x;
    return 0.5f * x * (1.0f + tanhf(0.7978845608028654f * (x + 0.044715f * x3)));
}

template<int MODE, int PREC>
__global__ void __launch_bounds__(256, 2) gemm_mma(
    const __nv_bfloat16* __restrict__ Ahi, const __nv_bfloat16* __restrict__ Alo,
    const __nv_bfloat16* __restrict__ Bhi, const __nv_bfloat16* __restrict__ Blo,
    const float* __restrict__ bias, float* __restrict__ Cf,
    __nv_bfloat16* __restrict__ Chi, __nv_bfloat16* __restrict__ Clo,
    int M, int N, int K)
{
    constexpr int NARR = (PREC == 0) ? 4 : 3;
    constexpr uint32_t STAGE_SZ = NARR * STG_B;
    extern __shared__ char sm[];
    uint32_t sb = smem_u32(sm);
    int tid = threadIdx.x, wid = tid >> 5, lane = tid & 31;
    int mrow = blockIdx.y * 128, ncol = blockIdx.x * 128;
    int wm = (wid >> 1) * 32;       // 4 m-warps
    int wn = (wid & 1) * 64;        // 2 n-warps

    // cp.async loader: thread -> (row, two 16B units) over 64B rows
    int lr = tid >> 1;
    int lu0 = (tid & 1) * 2;
    const __nv_bfloat16* gAh = Ahi + (size_t)(mrow + lr) * K;
    const __nv_bfloat16* gAl = Alo + (size_t)(mrow + lr) * K;
    const __nv_bfloat16* gBh = Bhi + (size_t)(ncol + lr) * K;
    const __nv_bfloat16* gBl = (PREC == 0) ? (Blo + (size_t)(ncol + lr) * K) : nullptr;

    int nch = K >> 5;

    const int m_off = ((lane >> 3) & 1) * 8 + (lane & 7);
    const int a_ku  = (lane >> 4);
    const int n_off = ((lane >> 4) << 3) + (lane & 7);
    const int b_ku  = ((lane >> 3) & 1);

    float acc[2][8][4] = {};

    // prologue: fill NSTAGES-1 stages
    #pragma unroll
    for (int c = 0; c < NSTAGES-1; c++) {
        uint32_t bufb = sb + c * STAGE_SZ;
        int koff = c << 5;
        #pragma unroll
        for (int j = 0; j < 2; j++) {
            int u = lu0 + j;
            uint32_t so = swz64(lr, u);
            int ge = koff + u * 8;
            cp16(bufb + 0*STG_B + so, gAh + ge);
            cp16(bufb + 1*STG_B + so, gAl + ge);
            cp16(bufb + 2*STG_B + so, gBh + ge);
            if (PREC == 0) cp16(bufb + 3*STG_B + so, gBl + ge);
        }
        cp_commit();
    }

    for (int c = 0; c < nch; c++) {
        cp_wait<NSTAGES-2>();
        __syncthreads();

        int cn = c + NSTAGES-1;
        if (cn < nch) {
            uint32_t bufb = sb + (cn % NSTAGES) * STAGE_SZ;
            int koff = cn << 5;
            #pragma unroll
            for (int j = 0; j < 2; j++) {
                int u = lu0 + j;
                uint32_t so = swz64(lr, u);
                int ge = koff + u * 8;
                cp16(bufb + 0*STG_B + so, gAh + ge);
                cp16(bufb + 1*STG_B + so, gAl + ge);
                cp16(bufb + 2*STG_B + so, gBh + ge);
                if (PREC == 0) cp16(bufb + 3*STG_B + so, gBl + ge);
            }
        }
        cp_commit();

        uint32_t base = sb + (c % NSTAGES) * STAGE_SZ;
        uint32_t aH = base, aL = base + STG_B, bH = base + 2*STG_B, bL = base + 3*STG_B;

        #pragma unroll
        for (int kk = 0; kk < 2; kk++) {
            uint32_t ah[2][4], al[2][4], bb[4][4];
            uint32_t offA[2], offB[4];
            #pragma unroll
            for (int t2 = 0; t2 < 2; t2++) {
                int r = wm + t2*16 + m_off;
                offA[t2] = swz64(r, kk*2 + a_ku);
                LDSM4(ah[t2][0], ah[t2][1], ah[t2][2], ah[t2][3], aH + offA[t2]);
                LDSM4(al[t2][0], al[t2][1], al[t2][2], al[t2][3], aL + offA[t2]);
            }
            #pragma unroll
            for (int p = 0; p < 4; p++) {
                int r = wn + p*16 + n_off;
                offB[p] = swz64(r, kk*2 + b_ku);
                LDSM4(bb[p][0], bb[p][1], bb[p][2], bb[p][3], bH + offB[p]);
            }
            if (PREC == 0) {
                // pass 1: Ahi*Bhi
                #pragma unroll
                for (int t2 = 0; t2 < 2; t2++)
                    #pragma unroll
                    for (int p = 0; p < 4; p++) {
                        MMA16816(acc[t2][2*p],   ah[t2], bb[p][0], bb[p][1]);
                        MMA16816(acc[t2][2*p+1], ah[t2], bb[p][2], bb[p][3]);
                    }
                // pass 2: Alo*Bhi
                #pragma unroll
                for (int t2 = 0; t2 < 2; t2++)
                    #pragma unroll
                    for (int p = 0; p < 4; p++) {
                        MMA16816(acc[t2][2*p],   al[t2], bb[p][0], bb[p][1]);
                        MMA16816(acc[t2][2*p+1], al[t2], bb[p][2], bb[p][3]);
                    }
                // pass 3: Ahi*Blo
                #pragma unroll
                for (int p = 0; p < 4; p++)
                    LDSM4(bb[p][0], bb[p][1], bb[p][2], bb[p][3], bL + offB[p]);
                #pragma unroll
                for (int t2 = 0; t2 < 2; t2++)
                    #pragma unroll
                    for (int p = 0; p < 4; p++) {
                        MMA16816(acc[t2][2*p],   ah[t2], bb[p][0], bb[p][1]);
                        MMA16816(acc[t2][2*p+1], ah[t2], bb[p][2], bb[p][3]);
                    }
            } else {
                // fp16 pass 1: Ahi*Bh
                #pragma unroll
                for (int t2 = 0; t2 < 2; t2++)
                    #pragma unroll
                    for (int p = 0; p < 4; p++) {
                        MMA16816H(acc[t2][2*p],   ah[t2], bb[p][0], bb[p][1]);
                        MMA16816H(acc[t2][2*p+1], ah[t2], bb[p][2], bb[p][3]);
                    }
                // fp16 pass 2: Alo*Bh
                #pragma unroll
                for (int t2 = 0; t2 < 2; t2++)
                    #pragma unroll
                    for (int p = 0; p < 4; p++) {
                        MMA16816H(acc[t2][2*p],   al[t2], bb[p][0], bb[p][1]);
                        MMA16816H(acc[t2][2*p+1], al[t2], bb[p][2], bb[p][3]);
                    }
            }
        }
    }

    // ---------------- epilogue ----------------
    #pragma unroll
    for (int t2 = 0; t2 < 2; t2++) {
        int row0 = mrow + wm + t2*16 + (lane >> 2);
        #pragma unroll
        for (int p8 = 0; p8 < 8; p8++) {
            int col = ncol + wn + p8*8 + (lane & 3)*2;
            #pragma unroll
            for (int half = 0; half < 2; half++) {
                int row = row0 + half*8;
                float v0 = acc[t2][p8][half*2 + 0];
                float v1 = acc[t2][p8][half*2 + 1];
                if (MODE == 0) {
                    int which = col >> 9;         // 0=q,1=k,2=v
                    int c2 = col & 511;
                    int b = row >> 12, s = row & 4095;
                    int hh = c2 >> 6, dd = c2 & 63;
                    float* dst = Cf + (size_t)which*BSE;
                    *(float2*)&dst[(((size_t)b*HH + hh)*SS + s)*64 + dd] = make_float2(v0, v1);
                } else if (MODE == 1) {
                    float2* pp = (float2*)&Cf[(size_t)row*N + col];
                    float2 t = *pp; t.x += v0; t.y += v1; *pp = t;
                } else if (MODE == 2) {
                    float y0 = gelu_f(v0 + bias[col]);
                    float y1 = gelu_f(v1 + bias[col+1]);
                    __half h0 = __float2half_rn(y0), h1 = __float2half_rn(y1);
                    __half2 hh2; hh2.x = h0; hh2.y = h1;
                    __half2 ll2;
                    ll2.x = __float2half_rn(y0 - __half2float(h0));
                    ll2.y = __float2half_rn(y1 - __half2float(h1));
                    size_t o = (size_t)row*N + col;
                    *(__half2*)&((__half*)Chi)[o] = hh2;
                    *(__half2*)&((__half*)Clo)[o] = ll2;
                } else {
                    float2* pp = (float2*)&Cf[(size_t)row*N + col];
                    float2 t = *pp;
                    t.x += v0 + bias[col]; t.y += v1 + bias[col+1];
                    *pp = t;
                }
            }
        }
    }
}

// ---------------- row norms ----------------
__global__ void rownorm_kernel(const float* __restrict__ a, float* __restrict__ n, int rows) {
    int gw = (blockIdx.x * blockDim.x + threadIdx.x) >> 5;
    int lane = threadIdx.x & 31;
    if (gw >= rows) return;
    const float* r = a + (size_t)gw * 64;
    float v = r[lane]*r[lane] + r[lane+32]*r[lane+32];
    #pragma unroll
    for (int o = 16; o; o >>= 1) v += __shfl_xor_sync(~0u, v, o);
    if (!lane) n[gw] = sqrtf(v);
}

// ---------------- cosine dists: 64 s-rows per block (means loaded once) ----------------
__global__ void dists_kernel(const float* __restrict__ q, const float* __restrict__ qn,
                             const float* __restrict__ means_l, const float* __restrict__ mn,
                             float* __restrict__ dists) {
    __shared__ float msm[64*65];
    __shared__ float qs[4*65];
    int bh = blockIdx.y;
    int h  = bh & 7;
    int tid = threadIdx.x;
    for (int e = tid; e < 4096; e += 256) {
        int c = e >> 6, d = e & 63;
        msm[c*65 + d] = means_l[(size_t)h*CC*DD + c*64 + d];
    }
    int sbase = blockIdx.x * 64;
    for (int sc4 = 0; sc4 < 64; sc4 += 4) {
        __syncthreads();
        {
            int si = tid >> 6, d = tid & 63;
            qs[si*65 + d] = q[((size_t)bh*SS + sbase + sc4 + si)*DD + d];
        }
        __syncthreads();
        int c = tid >> 2, si = tid & 3;
        int s = sbase + sc4 + si;
        float dot = 0.f;
        #pragma unroll
        for (int d = 0; d < 64; d++) dot += qs[si*65 + d] * msm[c*65 + d];
        float denom = (qn[(size_t)bh*SS + s] + 1e-8f) * (mn[h*CC + c] + 1e-8f);
        dists[((size_t)bh*CC + c)*SS + s] = dot / denom;
    }
}

// ---------------- top-64 per (b,h,c): RADIX SELECT ----------------
__global__ void topk_kernel(const float* __restrict__ dists, int* __restrict__ idx) {
    __shared__ uint32_t keys[SS];
    __shared__ int hist[256];
    __shared__ int ps[256];
    __shared__ int s_misc[4];
    int bid = blockIdx.x;
    int tid = threadIdx.x;
    const float* dr = dists + (size_t)bid * SS;

    for (int i = tid; i < SS; i += 256) {
        uint32_t b = __float_as_uint(dr[i]);
        keys[i] = (b & 0x80000000u) ? ~b : (b | 0x80000000u);
    }
    if (tid == 0) { s_misc[0] = 0; s_misc[1] = WW; s_misc[2] = 0; s_misc[3] = 0; }
    __syncthreads();

    #pragma unroll
    for (int bp = 3; bp >= 0; bp--) {
        int shift = bp * 8;
        uint32_t himask = (bp == 3) ? 0u : (0xFFFFFFFFu << (shift + 8));
        uint32_t prefix = (uint32_t)s_misc[0];
        hist[tid] = 0;
        __syncthreads();
        for (int i = tid; i < SS; i += 256) {
            uint32_t kk = keys[i];
            if ((kk & himask) == prefix)
                atomicAdd(&hist[(kk >> shift) & 255], 1);
        }
        __syncthreads();
        if (tid == 0) {
            int k = s_misc[1];
            int acc = 0;
            int d = 255;
            for (; d >= 0; d--) {
                acc += hist[d];
                if (acc >= k) break;
            }
            s_misc[1] = k - (acc - hist[d]);
            s_misc[0] = (int)(prefix | ((uint32_t)d << shift));
        }
        __syncthreads();
    }
    uint32_t T = (uint32_t)s_misc[0];

    for (int i = tid; i < SS; i += 256) {
        if (keys[i] > T) {
            int p = atomicAdd(&s_misc[2], 1);
            idx[bid*WW + p] = i;
        }
    }
    __syncthreads();
    int G = s_misc[2];
    int kneed = WW - G;

    for (int chunk = 0; chunk < SS; chunk += 256) {
        int i = chunk + tid;
        int pred = (keys[i] == T) ? 1 : 0;
        ps[tid] = pred;
        __syncthreads();
        #pragma unroll
        for (int off = 1; off < 256; off <<= 1) {
            int v = (tid >= off) ? ps[tid - off] : 0;
            __syncthreads();
            ps[tid] += v;
            __syncthreads();
        }
        int excl = ps[tid] - pred;
        int ebase = s_misc[3];
        if (pred && (ebase + excl) < kneed)
            idx[bid*WW + G + ebase + excl] = i;
        __syncthreads();
        if (tid == 0) s_misc[3] = ebase + ps[255];
        __syncthreads();
        if (s_misc[3] >= kneed) break;
    }
}

// ---------------- bucketed attention + scatter-add ----------------
#define ATTN_SMEM_BYTES ((128 + 4*64*65) * 4)
__global__ void attn_kernel(const float* __restrict__ q, const float* __restrict__ k,
                            const float* __restrict__ v, const int* __restrict__ value,
                            const int* __restrict__ idx, float* __restrict__ oacc,
                            float* __restrict__ cnt) {
    extern __shared__ float smf[];
    int*   ids = (int*)smf;
    float* km  = smf + 64;
    float* qb  = smf + 128;
    float* kb  = qb + 64*65;
    float* vb  = kb + 64*65;
    float* sc  = vb + 64*65;
    int bid = blockIdx.x;
    int bh  = bid >> 6;
    int b   = bid >> 9;
    int tid = threadIdx.x;
    if (tid < 64) {
        int g = idx[bid*WW + tid];
        ids[tid] = g;
        km[tid] = (value[b*SS + g] != 0) ? 1.f : 0.f;
    }
    __syncthreads();
    for (int e = tid; e < 4096; e += 256) {
        int i = e >> 6, d = e & 63;
        size_t base = ((size_t)bh*SS + ids[i])*DD + d;
        qb[i*65 + d] = q[base];
        kb[i*65 + d] = k[base];
        vb[i*65 + d] = v[base];
    }
    __syncthreads();
    for (int e = tid; e < 4096; e += 256) {
        int i = e >> 6, j = e & 63;
        float s = 0.f;
        #pragma unroll
        for (int d = 0; d < 64; d++) s += qb[i*65 + d] * kb[j*65 + d];
        bool allowed = (ids[i] >= ids[j]) && (km[j] > 0.5f);
        sc[i*65 + j] = allowed ? s * 0.125f : -1e9f;
    }
    __syncthreads();
    {
        int w = tid >> 5, lane = tid & 31;
        for (int r = 0; r < 8; r++) {
            int i = w*8 + r;
            float v0 = sc[i*65 + lane], v1 = sc[i*65 + lane + 32];
            float m = fmaxf(v0, v1);
            #pragma unroll
            for (int o = 16; o; o >>= 1) m = fmaxf(m, __shfl_xor_sync(~0u, m, o));
            float e0 = expf(v0 - m), e1 = expf(v1 - m);
            float su = e0 + e1;
            #pragma unroll
            for (int o = 16; o; o >>= 1) su += __shfl_xor_sync(~0u, su, o);
            float inv = 1.f / su;
            sc[i*65 + lane]      = e0 * inv;
            sc[i*65 + lane + 32] = e1 * inv;
        }
    }
    __syncthreads();
    for (int e = tid; e < 4096; e += 256) {
        int i = e >> 6, d = e & 63;
        float s = 0.f;
        #pragma unroll
        for (int j = 0; j < 64; j++) s += sc[i*65 + j] * vb[j*65 + d];
        int g = ids[i];
        atomicAdd(&oacc[((size_t)bh*SS + g)*DD + d], s);
        if (d == 0) atomicAdd(&cnt[(size_t)bh*SS + g], 1.f);
    }
}

// ---------------- scatter-mean finalize -> fp16 hi/lo (B,S,E) ----------------
__global__ void finalize_kernel(const float* __restrict__ oacc, const float* __restrict__ cnt,
                                __nv_bfloat16* __restrict__ ahi, __nv_bfloat16* __restrict__ alo) {
    int row = blockIdx.x;
    int b = row >> 12, s = row & 4095;
    for (int e = threadIdx.x; e < EE; e += blockDim.x) {
        int hh = e >> 6, d = e & 63;
        int bh = b*HH + hh;
        float c = cnt[(size_t)bh*SS + s];
        float v = oacc[((size_t)bh*SS + s)*DD + d] / fmaxf(c, 1.f);
        __half h = __float2half_rn(v);
        ((__half*)ahi)[(size_t)row*EE + e] = h;
        ((__half*)alo)[(size_t)row*EE + e] = __float2half_rn(v - __half2float(h));
    }
}

// ---------------- logit head ----------------
__global__ void head_kernel(const float* __restrict__ x, const float* __restrict__ hw,
                            float* __restrict__ out) {
    int row = blockIdx.x;
    int w = threadIdx.x >> 5, lane = threadIdx.x & 31;
    const float* xr = x + (size_t)row * EE;
    const float* wr = hw + (size_t)w * EE;
    float s = 0.f;
    for (int i = lane; i < EE; i += 32) s += xr[i] * wr[i];
    #pragma unroll
    for (int o = 16; o; o >>= 1) s += __shfl_xor_sync(~0u, s, o);
    if (!lane) out[(size_t)row*NVOC + w] = s;
}

// ---------------- host orchestration ----------------
extern "C" void kernel_launch(void* const* d_in, const int* in_sizes, int n_in,
                              void* d_out, int out_size) {
    const int*   value = (const int*)  d_in[0];
    const int*   depth = (const int*)  d_in[1];
    const int*   pos   = (const int*)  d_in[2];
    const float* sos   = (const float*)d_in[3];
    const float* tok   = (const float*)d_in[4];
    const float* dep   = (const float*)d_in[5];
    const float* pemb  = (const float*)d_in[6];
    const float* ln1s  = (const float*)d_in[7];
    const float* ln1b  = (const float*)d_in[8];
    const float* Wq    = (const float*)d_in[9];
    const float* Wk    = (const float*)d_in[10];
    const float* Wv    = (const float*)d_in[11];
    const float* Wo    = (const float*)d_in[12];
    const float* means = (const float*)d_in[13];
    const float* ln2s  = (const float*)d_in[14];
    const float* ln2b  = (const float*)d_in[15];
    const float* W1    = (const float*)d_in[16];
    const float* b1    = (const float*)d_in[17];
    const float* W2    = (const float*)d_in[18];
    const float* b2    = (const float*)d_in[19];
    const float* hw    = (const float*)d_in[20];
    float* out = (float*)d_out;

    float* base = nullptr;
    cudaGetSymbolAddress((void**)&base, g_buf);
    int* gidx = nullptr;
    cudaGetSymbolAddress((void**)&gidx, g_idx);
    __nv_bfloat16* wt = nullptr;
    cudaGetSymbolAddress((void**)&wt, g_wt);
    __nv_bfloat16* wt_lo = wt + WT_TOT;

    float* x     = base;
    __nv_bfloat16* h_hi = (__nv_bfloat16*)(base + 1*BSE);
    __nv_bfloat16* h_lo = h_hi + BSE;
    float* q     = base + 2*BSE;
    float* k     = base + 3*BSE;
    float* v     = base + 4*BSE;
    float* dists = base + 5*BSE;
    float* oacc  = base + 6*BSE;
    __nv_bfloat16* ab_hi = (__nv_bfloat16*)(base + 7*BSE);
    __nv_bfloat16* ab_lo = ab_hi + BSE;
    __nv_bfloat16* ff_hi = (__nv_bfloat16*)(base + 8*BSE);
    __nv_bfloat16* ff_lo = ff_hi + (size_t)BS*FF;
    float* qn    = base + 12*BSE;
    float* mn    = qn + BHS;
    float* cnt   = mn + 512;

    cudaFuncSetAttribute(attn_kernel, cudaFuncAttributeMaxDynamicSharedMemorySize, ATTN_SMEM_BYTES);
    cudaFuncSetAttribute(gemm_mma<0,0>, cudaFuncAttributeMaxDynamicSharedMemorySize, GT_SMEM0);
    cudaFuncSetAttribute(gemm_mma<1,1>, cudaFuncAttributeMaxDynamicSharedMemorySize, GT_SMEM1);
    cudaFuncSetAttribute(gemm_mma<2,1>, cudaFuncAttributeMaxDynamicSharedMemorySize, GT_SMEM1);
    cudaFuncSetAttribute(gemm_mma<3,1>, cudaFuncAttributeMaxDynamicSharedMemorySize, GT_SMEM1);

    wtrans_all<<<LL*3072, dim3(32,8)>>>(Wq, Wk, Wv, Wo, W1, W2, wt, wt_lo);
    embed_kernel<<<BS, 256>>>(value, depth, pos, sos, tok, dep, pemb, x);

    const int M = BS;
    dim3 gQKV(1536/128, M/128);    // fused QKV: N=1536
    dim3 g512(512/128, M/128);
    dim3 gFF(FF/128, M/128);

    for (int l = 0; l < LL; l++) {
        size_t lb = (size_t)l * WT_LAYER;
        const __nv_bfloat16* wqkv  = wt + lb;           // wq|wk|wv contiguous [1536, 512] bf16
        const __nv_bfloat16* wqkvl = wt_lo + lb;
        const __nv_bfloat16* wot = wt + lb + 786432;    // fp16 single
        const __nv_bfloat16* w1t = wt + lb + 1048576;   // fp16 single
        const __nv_bfloat16* w2t = wt + lb + 2097152;   // fp16 single
        const float* ml = means + (size_t)l*HH*CC*DD;

        ln_kernel<<<BS, 256>>>(x, ln1s + l*EE, ln1b + l*EE, h_hi, h_lo, 0);
        gemm_mma<0,0><<<gQKV, 256, GT_SMEM0>>>(h_hi, h_lo, wqkv, wqkvl, nullptr, q, nullptr, nullptr, M, 1536, 512);

        rownorm_kernel<<<(BHS*32)/256, 256>>>(q, qn, BHS);
        rownorm_kernel<<<(HH*CC*32)/256, 256>>>(ml, mn, HH*CC);
        dists_kernel<<<dim3(SS/64, BB*HH), 256>>>(q, qn, ml, mn, dists);
        topk_kernel<<<BB*HH*CC, 256>>>(dists, gidx);

        cudaMemsetAsync(oacc, 0, BSE * sizeof(float));
        cudaMemsetAsync(cnt, 0, BHS * sizeof(float));
        attn_kernel<<<BB*HH*CC, 256, ATTN_SMEM_BYTES>>>(q, k, v, value, gidx, oacc, cnt);
        finalize_kernel<<<BS, 256>>>(oacc, cnt, ab_hi, ab_lo);
        gemm_mma<1,1><<<g512, 256, GT_SMEM1>>>(ab_hi, ab_lo, wot, nullptr, nullptr, x, nullptr, nullptr, M, 512, 512);

        ln_kernel<<<BS, 256>>>(x, ln2s + l*EE, ln2b + l*EE, h_hi, h_lo, 1);
        gemm_mma<2,1><<<gFF, 256, GT_SMEM1>>>(h_hi, h_lo, w1t, nullptr, b1 + l*FF, nullptr, ff_hi, ff_lo, M, FF, 512);
        gemm_mma<3,1><<<g512, 256, GT_SMEM1>>>(ff_hi, ff_lo, w2t, nullptr, b2 + l*EE, x, nullptr, nullptr, M, 512, FF);
    }

    head_kernel<<<BS, NVOC*32>>>(x, hw, out);
}